// round 13
// baseline (speedup 1.0000x reference)
#include <cuda_runtime.h>

#define DIM 31
#define PAD 32
#define NMAX 500000
#define EMAX 2000000
#define GMAX 4096
#define BN_EPS 1e-5f
#define NPB_MAX 8192
#define RSTR 34  /* smem tile row stride in floats */

typedef unsigned long long u64;

#define PACK2(d, lo, hi) \
    asm("mov.b64 %0, {%1, %2};" : "=l"(d) : "r"(__float_as_uint(lo)), "r"(__float_as_uint(hi)))
#define UNPACK2(lo, hi, s)                                  \
    do {                                                    \
        unsigned _l, _h;                                    \
        asm("mov.b64 {%0, %1}, %2;" : "=r"(_l), "=r"(_h) : "l"(s)); \
        lo = __uint_as_float(_l);                           \
        hi = __uint_as_float(_h);                           \
    } while (0)
#define FMA2(d, a, b, c) \
    asm("fma.rn.f32x2 %0, %1, %2, %3;" : "=l"(d) : "l"(a), "l"(b), "l"(c))

// ---------------- scratch (both branches concatenated: 2N nodes) ----------------
// State contract: g_cnt, g_pooled, g_gcnt, g_total are ZERO at entry
// (zero-init at load; re-zeroed by k_out each run).
__device__ float g_y0[(size_t)2 * NMAX * PAD];
__device__ float g_y1[(size_t)2 * NMAX * PAD];
__device__ int   g_cnt[2 * NMAX];
__device__ int   g_rowptr[2 * NMAX];
__device__ int   g_cursor[2 * NMAX];          // after k_fill: == segment end
__device__ int   g_perm[2 * EMAX];
__device__ int   g_total;
__device__ float g_partial[(size_t)NPB_MAX * 64];
__device__ float g_sums[5 * 128];
__device__ float g_pooled[2 * GMAX * PAD];
__device__ float g_gcnt[2 * GMAX];
__device__ float g_ha[(size_t)2 * GMAX * 256];
__device__ float g_c1[(size_t)GMAX * 1024];
__device__ float g_c2[GMAX * 256];

// ---------------- count in-degree (g_cnt pre-zeroed) ----------------
__global__ void k_count(const int* __restrict__ dsta, const int* __restrict__ dstb,
                        int E, int N) {
    for (int e = blockIdx.x * blockDim.x + threadIdx.x; e < 2 * E;
         e += gridDim.x * blockDim.x) {
        int d = (e < E) ? __ldg(dsta + e) : (__ldg(dstb + e - E) + N);
        atomicAdd(&g_cnt[d], 1);
    }
}

// ---------------- scan-free segment assignment + pack x into y0 ----------------
__global__ void k_assign(const float* __restrict__ xa, const float* __restrict__ xb,
                         int N, int NN) {
    __shared__ int s[512];
    __shared__ int sbase;
    int i = blockIdx.x * 512 + threadIdx.x;
    int c = (i < NN) ? g_cnt[i] : 0;
    s[threadIdx.x] = c;
    __syncthreads();
    for (int o = 1; o < 512; o <<= 1) {
        int t = (threadIdx.x >= o) ? s[threadIdx.x - o] : 0;
        __syncthreads();
        s[threadIdx.x] += t;
        __syncthreads();
    }
    if (threadIdx.x == 511) sbase = atomicAdd(&g_total, s[511]);
    __syncthreads();
    int ex = s[threadIdx.x] - c + sbase;
    if (i < NN) {
        g_rowptr[i] = ex;
        g_cursor[i] = ex;
    }
    int stride = gridDim.x * blockDim.x;
    int tid0 = blockIdx.x * blockDim.x + threadIdx.x;
    int total = N * PAD;
    for (int t = tid0; t < total; t += stride) {
        int cc = t & (PAD - 1);
        int ii = t >> 5;
        g_y0[t] = (cc < DIM) ? xa[ii * DIM + cc] : 0.f;
        g_y0[(size_t)N * PAD + t] = (cc < DIM) ? xb[ii * DIM + cc] : 0.f;
    }
}

// ---------------- fill CSR (g_cursor -> segment ends) ----------------
__global__ void k_fill(const int* __restrict__ srca, const int* __restrict__ dsta,
                       const int* __restrict__ srcb, const int* __restrict__ dstb,
                       int E, int N) {
    for (int e = blockIdx.x * blockDim.x + threadIdx.x; e < 2 * E;
         e += gridDim.x * blockDim.x) {
        int d, s;
        if (e < E) {
            d = __ldg(dsta + e);
            s = __ldg(srca + e);
        } else {
            d = __ldg(dstb + e - E) + N;
            s = __ldg(srcb + e - E) + N;
        }
        int p = atomicAdd(&g_cursor[d], 1);
        g_perm[p] = s;
    }
}

// ---------------- fused: coalesced gather->tile, register-light MLP, stats, pool ----------------
__global__ void __launch_bounds__(128, 4)
k_gmlp(const float* __restrict__ yin, float* __restrict__ yout,
       const float* __restrict__ W1, const float* __restrict__ b1,
       const float* __restrict__ W2, const float* __restrict__ b2,
       const float* __restrict__ gammaP, const float* __restrict__ betaP,
       const float* __restrict__ sumsPA, const float* __restrict__ sumsPB,
       float* __restrict__ partial,
       const int* __restrict__ batchA, const int* __restrict__ batchB,
       int N, int G, int NPBh, float invN) {
    __shared__ float hid[256 * RSTR];           // 34.0 KB tile (inputs -> hidden -> outputs)
    __shared__ ulonglong2 sW1x[31 * 8], sW2x[31 * 8];
    __shared__ u64 sb1p[16], sb2p[16];
    __shared__ float ssc[32], ssf[32];
    __shared__ float sstat[16 * 64];

    bool brB = blockIdx.x >= NPBh;
    const float* sumsP = brB ? sumsPB : sumsPA;

    for (int idx = threadIdx.x; idx < 31 * 8; idx += 128) {
        int i = idx >> 3, q = idx & 7;
        int c0 = 4 * q;
        float w0 = W1[i * 31 + c0];
        float w1 = (c0 + 1 < 31) ? W1[i * 31 + c0 + 1] : 0.f;
        float w2 = (c0 + 2 < 31) ? W1[i * 31 + c0 + 2] : 0.f;
        float w3 = (c0 + 3 < 31) ? W1[i * 31 + c0 + 3] : 0.f;
        ulonglong2 pp;
        PACK2(pp.x, w0, w1);
        PACK2(pp.y, w2, w3);
        sW1x[idx] = pp;
        w0 = W2[i * 31 + c0];
        w1 = (c0 + 1 < 31) ? W2[i * 31 + c0 + 1] : 0.f;
        w2 = (c0 + 2 < 31) ? W2[i * 31 + c0 + 2] : 0.f;
        w3 = (c0 + 3 < 31) ? W2[i * 31 + c0 + 3] : 0.f;
        PACK2(pp.x, w0, w1);
        PACK2(pp.y, w2, w3);
        sW2x[idx] = pp;
    }
    if (threadIdx.x < 16) {
        int o = threadIdx.x;
        float lo = b1[2 * o];
        float hi = (2 * o + 1 < 31) ? b1[2 * o + 1] : 0.f;
        u64 p;
        PACK2(p, lo, hi);
        sb1p[o] = p;
        lo = b2[2 * o];
        hi = (2 * o + 1 < 31) ? b2[2 * o + 1] : 0.f;
        PACK2(p, lo, hi);
        sb2p[o] = p;
    }
    if (threadIdx.x < 32) {
        int c = threadIdx.x;
        float sc = 0.f, sf = 0.f;
        if (c < DIM) {
            sc = 1.f;
            if (sumsP) {
                float m = sumsP[c] * invN;
                float var = sumsP[PAD + c] * invN - m * m;
                float istd = rsqrtf(var + BN_EPS);
                sc = gammaP[c] * istd;
                sf = betaP[c] - m * sc;
            }
        }
        ssc[c] = sc;
        ssf[c] = sf;
    }
    __syncthreads();

    int blk = brB ? (blockIdx.x - NPBh) : blockIdx.x;
    int base = blk * 256;
    int off = brB ? N : 0;

    // ---- phase A: coalesced gather + BN affine (incl. deg term) into tile ----
    {
        int gg = threadIdx.x & 7;   // column group (4 floats)
        int sub = threadIdx.x >> 3; // 0..15
        int c0 = gg * 4;
        float sc0 = ssc[c0], sc1 = ssc[c0 + 1], sc2 = ssc[c0 + 2], sc3 = ssc[c0 + 3];
        float sf0 = ssf[c0], sf1 = ssf[c0 + 1], sf2 = ssf[c0 + 2], sf3 = ssf[c0 + 3];
#pragma unroll 1
        for (int pass = 0; pass < 16; pass++) {
            int ln = pass * 16 + sub;
            int lnode = base + ln;
            int n = ((lnode < N) ? lnode : (N - 1)) + off;
            float4 acc = *(const float4*)(yin + (size_t)n * PAD + c0);
            int beg = __ldg(g_rowptr + n), end = __ldg(g_cursor + n);
            int p = beg;
            for (; p + 1 < end; p += 2) {
                int s0 = __ldg(g_perm + p);
                int s1 = __ldg(g_perm + p + 1);
                float4 v0 = *(const float4*)(yin + (size_t)s0 * PAD + c0);
                float4 v1 = *(const float4*)(yin + (size_t)s1 * PAD + c0);
                acc.x += v0.x + v1.x;
                acc.y += v0.y + v1.y;
                acc.z += v0.z + v1.z;
                acc.w += v0.w + v1.w;
            }
            if (p < end) {
                int s0 = __ldg(g_perm + p);
                float4 v0 = *(const float4*)(yin + (size_t)s0 * PAD + c0);
                acc.x += v0.x;
                acc.y += v0.y;
                acc.z += v0.z;
                acc.w += v0.w;
            }
            float dp1 = (float)(end - beg) + 1.f;
            float* hp = hid + ln * RSTR + c0;
            *(float2*)(hp) = make_float2(sc0 * acc.x + dp1 * sf0,
                                         sc1 * acc.y + dp1 * sf1);
            *(float2*)(hp + 2) = make_float2(sc2 * acc.z + dp1 * sf2,
                                             sc3 * acc.w + dp1 * sf3);
        }
    }
    __syncthreads();

    // ---- phase B: thread t owns tile rows t and t+128 (register-light) ----
    int t = threadIdx.x;
    int lnA = base + t, lnB = base + 128 + t;
    bool actA = lnA < N, actB = lnB < N;

    bool doPool = (batchA != nullptr);
    int bA = -1, bB = -1;
    if (doPool) {
        if (actA) bA = brB ? (__ldg(batchB + lnA) + G) : __ldg(batchA + lnA);
        if (actB) bB = brB ? (__ldg(batchB + lnB) + G) : __ldg(batchA + lnB);
    }
    int b0 = __shfl_sync(0xffffffffu, bA, 0);
    bool uniform = doPool && (b0 >= 0) &&
                   __all_sync(0xffffffffu,
                              ((bA == b0) || (bA < 0)) && ((bB == b0) || (bB < 0)));
    int cntAct = __popc(__ballot_sync(0xffffffffu, actA)) +
                 __popc(__ballot_sync(0xffffffffu, actB));

    // layer 1 (per node, streamed inputs, single acc[16])
#pragma unroll 1
    for (int sel = 0; sel < 2; sel++) {
        int row = sel ? (128 + t) : t;
        const u64* hr = (const u64*)(hid + row * RSTR);
        u64 acc[16];
#pragma unroll
        for (int o = 0; o < 16; o++) acc[o] = sb1p[o];
#pragma unroll
        for (int j = 0; j < 16; j++) {
            u64 hj = hr[j];
            float x0, x1;
            UNPACK2(x0, x1, hj);
            u64 xp;
            PACK2(xp, x0, x0);
            const ulonglong2* wr = sW1x + (2 * j) * 8;
#pragma unroll
            for (int q = 0; q < 8; q++) {
                ulonglong2 wv = wr[q];
                FMA2(acc[2 * q], xp, wv.x, acc[2 * q]);
                FMA2(acc[2 * q + 1], xp, wv.y, acc[2 * q + 1]);
            }
            if (j < 15) {
                PACK2(xp, x1, x1);
                wr = sW1x + (2 * j + 1) * 8;
#pragma unroll
                for (int q = 0; q < 8; q++) {
                    ulonglong2 wv = wr[q];
                    FMA2(acc[2 * q], xp, wv.x, acc[2 * q]);
                    FMA2(acc[2 * q + 1], xp, wv.y, acc[2 * q + 1]);
                }
            }
        }
        u64* hw = (u64*)(hid + row * RSTR);
#pragma unroll
        for (int o = 0; o < 16; o++) {
            float lo, hi;
            UNPACK2(lo, hi, acc[o]);
            u64 pk;
            PACK2(pk, fmaxf(lo, 0.f), fmaxf(hi, 0.f));
            hw[o] = pk;
        }
    }

    // layer 2 (per node, single acc[16]; relu+mask -> tile)
#pragma unroll 1
    for (int sel = 0; sel < 2; sel++) {
        int row = sel ? (128 + t) : t;
        float am = (sel ? actB : actA) ? 1.f : 0.f;
        const u64* hr = (const u64*)(hid + row * RSTR);
        u64 acc[16];
#pragma unroll
        for (int o = 0; o < 16; o++) acc[o] = sb2p[o];
#pragma unroll
        for (int j = 0; j < 16; j++) {
            u64 hj = hr[j];
            float x0, x1;
            UNPACK2(x0, x1, hj);
            u64 xp;
            PACK2(xp, x0, x0);
            const ulonglong2* wr = sW2x + (2 * j) * 8;
#pragma unroll
            for (int q = 0; q < 8; q++) {
                ulonglong2 wv = wr[q];
                FMA2(acc[2 * q], xp, wv.x, acc[2 * q]);
                FMA2(acc[2 * q + 1], xp, wv.y, acc[2 * q + 1]);
            }
            if (j < 15) {
                PACK2(xp, x1, x1);
                wr = sW2x + (2 * j + 1) * 8;
#pragma unroll
                for (int q = 0; q < 8; q++) {
                    ulonglong2 wv = wr[q];
                    FMA2(acc[2 * q], xp, wv.x, acc[2 * q]);
                    FMA2(acc[2 * q + 1], xp, wv.y, acc[2 * q + 1]);
                }
            }
        }
        u64* hw = (u64*)(hid + row * RSTR);
#pragma unroll
        for (int o = 0; o < 16; o++) {
            float lo, hi;
            UNPACK2(lo, hi, acc[o]);
            lo = fmaxf(lo, 0.f) * am;
            hi = fmaxf(hi, 0.f) * am;
            if (o == 15) hi = 0.f;
            u64 pk;
            PACK2(pk, lo, hi);
            hw[o] = pk;
        }
    }

    // ---- stats (+pool) pass: re-read own tile rows ----
    {
        int wid = threadIdx.x >> 5, lane = threadIdx.x & 31;
        const u64* hrA = (const u64*)(hid + t * RSTR);
        const u64* hrB = (const u64*)(hid + (128 + t) * RSTR);
#pragma unroll
        for (int o = 0; o < 16; o++) {
            float loA, hiA, loB, hiB;
            UNPACK2(loA, hiA, hrA[o]);
            UNPACK2(loB, hiB, hrB[o]);
            float s0 = loA + loB, q0 = loA * loA + loB * loB;
            float s1 = hiA + hiB, q1 = hiA * hiA + hiB * hiB;
#pragma unroll
            for (int offX = 16; offX >= 4; offX >>= 1) {
                s0 += __shfl_xor_sync(0xffffffffu, s0, offX);
                q0 += __shfl_xor_sync(0xffffffffu, q0, offX);
                s1 += __shfl_xor_sync(0xffffffffu, s1, offX);
                q1 += __shfl_xor_sync(0xffffffffu, q1, offX);
            }
            if (lane < 4) {
                sstat[(wid * 4 + lane) * 64 + 2 * o + 0] = s0;
                sstat[(wid * 4 + lane) * 64 + 32 + 2 * o + 0] = q0;
                sstat[(wid * 4 + lane) * 64 + 2 * o + 1] = s1;
                sstat[(wid * 4 + lane) * 64 + 32 + 2 * o + 1] = q1;
            }
            if (doPool) {
                if (uniform) {
                    s0 += __shfl_xor_sync(0xffffffffu, s0, 2);
                    s0 += __shfl_xor_sync(0xffffffffu, s0, 1);
                    s1 += __shfl_xor_sync(0xffffffffu, s1, 2);
                    s1 += __shfl_xor_sync(0xffffffffu, s1, 1);
                    if (lane == 0) {
                        atomicAdd(&g_pooled[(size_t)b0 * PAD + 2 * o], s0);
                        if (2 * o + 1 < DIM)
                            atomicAdd(&g_pooled[(size_t)b0 * PAD + 2 * o + 1], s1);
                    }
                } else {
                    if (actA) {
                        atomicAdd(&g_pooled[(size_t)bA * PAD + 2 * o], loA);
                        if (2 * o + 1 < DIM)
                            atomicAdd(&g_pooled[(size_t)bA * PAD + 2 * o + 1], hiA);
                    }
                    if (actB) {
                        atomicAdd(&g_pooled[(size_t)bB * PAD + 2 * o], loB);
                        if (2 * o + 1 < DIM)
                            atomicAdd(&g_pooled[(size_t)bB * PAD + 2 * o + 1], hiB);
                    }
                }
            }
        }
        if (doPool) {
            if (uniform) {
                if (lane == 0) atomicAdd(&g_gcnt[b0], (float)cntAct);
            } else {
                if (actA) atomicAdd(&g_gcnt[bA], 1.f);
                if (actB) atomicAdd(&g_gcnt[bB], 1.f);
            }
        }
    }
    __syncthreads();

    // ---- coalesced store of the tile ----
    {
        int gg = threadIdx.x & 7;
        int sub = threadIdx.x >> 3;
#pragma unroll 1
        for (int pass = 0; pass < 16; pass++) {
            int ln = pass * 16 + sub;
            int lnode = base + ln;
            if (lnode < N) {
                const float* hp = hid + ln * RSTR + gg * 4;
                float2 v0 = *(const float2*)(hp);
                float2 v1 = *(const float2*)(hp + 2);
                *(float4*)(yout + (size_t)(lnode + off) * PAD + gg * 4) =
                    make_float4(v0.x, v0.y, v1.x, v1.y);
            }
        }
    }

    if (threadIdx.x < 64) {
        float tt = 0.f;
#pragma unroll
        for (int r = 0; r < 16; r++) tt += sstat[r * 64 + threadIdx.x];
        partial[(size_t)blockIdx.x * 64 + threadIdx.x] = tt;
    }
}

// ---------------- reduce partials: 128 slots (A:0-63, B:64-127) ----------------
__global__ void k_reduce(float* __restrict__ out, int NPBh) {
    int blk = blockIdx.x;
    int slot = blk & 63;
    int start = (blk >= 64) ? NPBh : 0;
    float s = 0.f;
    for (int i = threadIdx.x; i < NPBh; i += blockDim.x)
        s += g_partial[(size_t)(start + i) * 64 + slot];
#pragma unroll
    for (int o = 16; o > 0; o >>= 1) s += __shfl_xor_sync(0xffffffffu, s, o);
    __shared__ float sh[8];
    if ((threadIdx.x & 31) == 0) sh[threadIdx.x >> 5] = s;
    __syncthreads();
    if (threadIdx.x == 0) {
        float t = 0.f;
#pragma unroll
        for (int w = 0; w < 8; w++) t += sh[w];
        out[blk] = t;
    }
}

// ---------------- per-graph fc with per-branch layer-4 BN affine ----------------
__global__ void k_fcbr(const float* __restrict__ W, const float* __restrict__ bb,
                       const float* __restrict__ gamma4, const float* __restrict__ beta4,
                       float* __restrict__ out, int G, float invN) {
    __shared__ float p[PAD];
    int g = blockIdx.x;
    if (threadIdx.x < PAD) {
        int c = threadIdx.x;
        float val = 0.f;
        if (c < DIM) {
            const float* s = g_sums + 4 * 128 + ((g >= G) ? 64 : 0);
            float m = s[c] * invN;
            float var = s[PAD + c] * invN - m * m;
            float istd = rsqrtf(var + BN_EPS);
            float sc = gamma4[c] * istd;
            float sf = beta4[c] - m * sc;
            val = g_pooled[(size_t)g * PAD + c] * sc + g_gcnt[g] * sf;
        }
        p[c] = val;
    }
    __syncthreads();
    int o = threadIdx.x;
    float acc = __ldg(bb + o);
#pragma unroll
    for (int i = 0; i < DIM; i++) acc += p[i] * __ldg(W + i * 256 + o);
    out[(size_t)g * 256 + o] = fmaxf(acc, 0.f);
}

// ---------------- tiled SGEMM (f32x2): C = act((A [+A2]) @ B + bias) ----------------
template <bool SUM2, bool RELU>
__global__ void k_gemm(const float* __restrict__ A, const float* __restrict__ A2,
                       const float* __restrict__ B, const float* __restrict__ bias,
                       float* __restrict__ C, int M, int N, int K) {
    const int BM = 64, BN = 64, BK = 16;
    __shared__ float As[BM][BK + 1];
    __shared__ float Bs[BK][BN];
    int tx = threadIdx.x % 16, ty = threadIdx.x / 16;
    int row0 = blockIdx.y * BM, col0 = blockIdx.x * BN;
    u64 acc2[4][2];
    u64 zero;
    PACK2(zero, 0.f, 0.f);
#pragma unroll
    for (int u = 0; u < 4; u++) {
        acc2[u][0] = zero;
        acc2[u][1] = zero;
    }
    for (int k0 = 0; k0 < K; k0 += BK) {
        for (int i = threadIdx.x; i < BM * BK; i += 256) {
            int r = i / BK, c = i % BK;
            float v = A[(size_t)(row0 + r) * K + k0 + c];
            if (SUM2) v += A2[(size_t)(row0 + r) * K + k0 + c];
            As[r][c] = v;
        }
        for (int i = threadIdx.x; i < BK * BN; i += 256) {
            int r = i / BN, c = i % BN;
            Bs[r][c] = B[(size_t)(k0 + r) * N + col0 + c];
        }
        __syncthreads();
#pragma unroll
        for (int k = 0; k < BK; k++) {
            u64 b0 = *(const u64*)&Bs[k][tx * 4];
            u64 b1 = *(const u64*)&Bs[k][tx * 4 + 2];
#pragma unroll
            for (int u = 0; u < 4; u++) {
                float a = As[ty * 4 + u][k];
                u64 ap;
                PACK2(ap, a, a);
                FMA2(acc2[u][0], ap, b0, acc2[u][0]);
                FMA2(acc2[u][1], ap, b1, acc2[u][1]);
            }
        }
        __syncthreads();
    }
#pragma unroll
    for (int u = 0; u < 4; u++) {
        int r = row0 + ty * 4 + u;
#pragma unroll
        for (int w = 0; w < 2; w++) {
            float lo, hi;
            UNPACK2(lo, hi, acc2[u][w]);
            int cc = col0 + tx * 4 + 2 * w;
            float v0 = lo + bias[cc];
            float v1 = hi + bias[cc + 1];
            if (RELU) {
                v0 = fmaxf(v0, 0.f);
                v1 = fmaxf(v1, 0.f);
            }
            C[(size_t)r * N + cc] = v0;
            C[(size_t)r * N + cc + 1] = v1;
        }
    }
}

// ---------------- final projection + restore zero-state for next replay ----------------
__global__ void k_out(const float* __restrict__ W, const float* __restrict__ b,
                      float* __restrict__ out, int G, int NN) {
    __shared__ float sW[512];
    for (int i = threadIdx.x; i < 512; i += blockDim.x) sW[i] = W[i];
    __syncthreads();
    int g = blockIdx.x * blockDim.x + threadIdx.x;
    if (g < G) {
        const float4* row = (const float4*)(g_c2 + (size_t)g * 256);
        float a0 = b[0], a1 = b[1];
#pragma unroll 8
        for (int i = 0; i < 64; i++) {
            float4 v = row[i];
            int o = i * 4;
            a0 += v.x * sW[2 * o + 0] + v.y * sW[2 * o + 2] + v.z * sW[2 * o + 4] + v.w * sW[2 * o + 6];
            a1 += v.x * sW[2 * o + 1] + v.y * sW[2 * o + 3] + v.z * sW[2 * o + 5] + v.w * sW[2 * o + 7];
        }
        out[g * 2 + 0] = a0;
        out[g * 2 + 1] = a1;
    }
    int stride = gridDim.x * blockDim.x;
    int tid0 = blockIdx.x * blockDim.x + threadIdx.x;
    for (int t = tid0; t < NN; t += stride) g_cnt[t] = 0;
    for (int t = tid0; t < 2 * GMAX * PAD; t += stride) g_pooled[t] = 0.f;
    for (int t = tid0; t < 2 * GMAX; t += stride) g_gcnt[t] = 0.f;
    if (tid0 == 0) g_total = 0;
}

// ---------------- launch ----------------
extern "C" void kernel_launch(void* const* d_in, const int* in_sizes, int n_in,
                              void* d_out, int out_size) {
    const float* x_a = (const float*)d_in[0];
    const int* ei_a = (const int*)d_in[1];
    const int* batch_a = (const int*)d_in[2];
    const float* x_b = (const float*)d_in[3];
    const int* ei_b = (const int*)d_in[4];
    const int* batch_b = (const int*)d_in[5];
    const float* W1s = (const float*)d_in[6];
    const float* b1s = (const float*)d_in[7];
    const float* W2s = (const float*)d_in[8];
    const float* b2s = (const float*)d_in[9];
    const float* gammas = (const float*)d_in[10];
    const float* betas = (const float*)d_in[11];
    const float* fcxW = (const float*)d_in[12];
    const float* fcxb = (const float*)d_in[13];
    const float* fc1W = (const float*)d_in[14];
    const float* fc1b = (const float*)d_in[15];
    const float* fc2W = (const float*)d_in[16];
    const float* fc2b = (const float*)d_in[17];
    const float* outW = (const float*)d_in[18];
    const float* outb = (const float*)d_in[19];

    int N = in_sizes[0] / DIM;
    int E = in_sizes[1] / 2;
    int G = out_size / 2;
    int NN = 2 * N;
    float invN = 1.f / (float)N;
    int NPBh = (N + 255) / 256;

    float* sums_ptr;
    float* ha_ptr;
    float* c1_ptr;
    float* c2_ptr;
    float* partial_ptr;
    float* y0_ptr;
    float* y1_ptr;
    cudaGetSymbolAddress((void**)&sums_ptr, g_sums);
    cudaGetSymbolAddress((void**)&ha_ptr, g_ha);
    cudaGetSymbolAddress((void**)&c1_ptr, g_c1);
    cudaGetSymbolAddress((void**)&c2_ptr, g_c2);
    cudaGetSymbolAddress((void**)&partial_ptr, g_partial);
    cudaGetSymbolAddress((void**)&y0_ptr, g_y0);
    cudaGetSymbolAddress((void**)&y1_ptr, g_y1);
    float* ybuf[2] = {y0_ptr, y1_ptr};

    k_count<<<2048, 256>>>(ei_a + E, ei_b + E, E, N);
    k_assign<<<(NN + 511) / 512, 512>>>(x_a, x_b, N, NN);
    k_fill<<<2048, 256>>>(ei_a, ei_a + E, ei_b, ei_b + E, E, N);

    for (int l = 0; l < 5; l++) {
        const float* sA = (l == 0) ? nullptr : sums_ptr + (l - 1) * 128;
        const float* sB = (l == 0) ? nullptr : sums_ptr + (l - 1) * 128 + 64;
        const float* gP = (l == 0) ? nullptr : gammas + (l - 1) * DIM;
        const float* bP = (l == 0) ? nullptr : betas + (l - 1) * DIM;
        const int* pA = (l == 4) ? batch_a : nullptr;
        const int* pB = (l == 4) ? batch_b : nullptr;
        k_gmlp<<<2 * NPBh, 128>>>(ybuf[l & 1], ybuf[1 - (l & 1)],
                                  W1s + l * DIM * DIM, b1s + l * DIM,
                                  W2s + l * DIM * DIM, b2s + l * DIM,
                                  gP, bP, sA, sB, partial_ptr, pA, pB,
                                  N, G, NPBh, invN);
        k_reduce<<<128, 256>>>(sums_ptr + l * 128, NPBh);
    }

    k_fcbr<<<2 * G, 256>>>(fcxW, fcxb, gammas + 4 * DIM, betas + 4 * DIM,
                           ha_ptr, G, invN);

    dim3 g1(1024 / 64, G / 64);
    k_gemm<true, true><<<g1, 256>>>(ha_ptr, ha_ptr + (size_t)G * 256, fc1W, fc1b,
                                    c1_ptr, G, 1024, 256);
    dim3 g2(256 / 64, G / 64);
    k_gemm<false, true><<<g2, 256>>>(c1_ptr, nullptr, fc2W, fc2b, c2_ptr, G, 256, 1024);
    k_out<<<1024, 256>>>(outW, outb, (float*)d_out, G, NN);
}

// round 14
// speedup vs baseline: 3.7014x; 3.7014x over previous
#include <cuda_runtime.h>

#define DIM 31
#define PAD 32
#define NMAX 500000
#define EMAX 2000000
#define GMAX 4096
#define BN_EPS 1e-5f
#define NPB_MAX 8192
#define RSTR 34  /* tile row stride in floats (136B, 8B-aligned rows) */

typedef unsigned long long u64;

#define PACK2(d, lo, hi) \
    asm("mov.b64 %0, {%1, %2};" : "=l"(d) : "r"(__float_as_uint(lo)), "r"(__float_as_uint(hi)))
#define UNPACK2(lo, hi, s)                                  \
    do {                                                    \
        unsigned _l, _h;                                    \
        asm("mov.b64 {%0, %1}, %2;" : "=r"(_l), "=r"(_h) : "l"(s)); \
        lo = __uint_as_float(_l);                           \
        hi = __uint_as_float(_h);                           \
    } while (0)
#define FMA2(d, a, b, c) \
    asm("fma.rn.f32x2 %0, %1, %2, %3;" : "=l"(d) : "l"(a), "l"(b), "l"(c))

// ---------------- scratch (both branches concatenated: 2N nodes) ----------------
// State contract: g_cnt, g_pooled, g_gcnt, g_total are ZERO at entry
// (zero-init at load; re-zeroed by k_out each run).
__device__ float g_y0[(size_t)2 * NMAX * PAD];
__device__ float g_y1[(size_t)2 * NMAX * PAD];
__device__ int   g_cnt[2 * NMAX];
__device__ int   g_rowptr[2 * NMAX];
__device__ int   g_cursor[2 * NMAX];          // after k_fill: == segment end
__device__ int   g_perm[2 * EMAX];
__device__ int   g_total;
__device__ float g_partial[(size_t)NPB_MAX * 64];
__device__ float g_sums[5 * 128];
__device__ float g_pooled[2 * GMAX * PAD];
__device__ float g_gcnt[2 * GMAX];
__device__ float g_ha[(size_t)2 * GMAX * 256];
__device__ float g_c1[(size_t)GMAX * 1024];
__device__ float g_c2[GMAX * 256];

// ---------------- count in-degree (g_cnt pre-zeroed) ----------------
__global__ void k_count(const int* __restrict__ dsta, const int* __restrict__ dstb,
                        int E, int N) {
    for (int e = blockIdx.x * blockDim.x + threadIdx.x; e < 2 * E;
         e += gridDim.x * blockDim.x) {
        int d = (e < E) ? __ldg(dsta + e) : (__ldg(dstb + e - E) + N);
        atomicAdd(&g_cnt[d], 1);
    }
}

// ---------------- scan-free segment assignment + pack x into y0 ----------------
__global__ void k_assign(const float* __restrict__ xa, const float* __restrict__ xb,
                         int N, int NN) {
    __shared__ int s[512];
    __shared__ int sbase;
    int i = blockIdx.x * 512 + threadIdx.x;
    int c = (i < NN) ? g_cnt[i] : 0;
    s[threadIdx.x] = c;
    __syncthreads();
    for (int o = 1; o < 512; o <<= 1) {
        int t = (threadIdx.x >= o) ? s[threadIdx.x - o] : 0;
        __syncthreads();
        s[threadIdx.x] += t;
        __syncthreads();
    }
    if (threadIdx.x == 511) sbase = atomicAdd(&g_total, s[511]);
    __syncthreads();
    int ex = s[threadIdx.x] - c + sbase;
    if (i < NN) {
        g_rowptr[i] = ex;
        g_cursor[i] = ex;
    }
    int stride = gridDim.x * blockDim.x;
    int tid0 = blockIdx.x * blockDim.x + threadIdx.x;
    int total = N * PAD;
    for (int t = tid0; t < total; t += stride) {
        int cc = t & (PAD - 1);
        int ii = t >> 5;
        g_y0[t] = (cc < DIM) ? xa[ii * DIM + cc] : 0.f;
        g_y0[(size_t)N * PAD + t] = (cc < DIM) ? xb[ii * DIM + cc] : 0.f;
    }
}

// ---------------- fill CSR (g_cursor -> segment ends) ----------------
__global__ void k_fill(const int* __restrict__ srca, const int* __restrict__ dsta,
                       const int* __restrict__ srcb, const int* __restrict__ dstb,
                       int E, int N) {
    for (int e = blockIdx.x * blockDim.x + threadIdx.x; e < 2 * E;
         e += gridDim.x * blockDim.x) {
        int d, s;
        if (e < E) {
            d = __ldg(dsta + e);
            s = __ldg(srca + e);
        } else {
            d = __ldg(dstb + e - E) + N;
            s = __ldg(srcb + e - E) + N;
        }
        int p = atomicAdd(&g_cursor[d], 1);
        g_perm[p] = s;
    }
}

// ---------------- fused: coalesced gather->tile, round-9 register MLP ----------------
__global__ void __launch_bounds__(128, 3)
k_gmlp(const float* __restrict__ yin, float* __restrict__ yout,
       const float* __restrict__ W1, const float* __restrict__ b1,
       const float* __restrict__ W2, const float* __restrict__ b2,
       const float* __restrict__ gammaP, const float* __restrict__ betaP,
       const float* __restrict__ sumsPA, const float* __restrict__ sumsPB,
       float* __restrict__ partial,
       const int* __restrict__ batchA, const int* __restrict__ batchB,
       int N, int G, int NPBh, float invN) {
    __shared__ float hid[256 * RSTR];           // 34.0 KB gathered-input tile
    __shared__ ulonglong2 sW1x[31 * 8], sW2x[31 * 8];
    __shared__ u64 sb1p[16], sb2p[16];
    __shared__ float ssc[32], ssf[32];
    __shared__ float sstat[16 * 64];

    bool brB = blockIdx.x >= NPBh;
    const float* sumsP = brB ? sumsPB : sumsPA;

    for (int idx = threadIdx.x; idx < 31 * 8; idx += 128) {
        int i = idx >> 3, q = idx & 7;
        int c0 = 4 * q;
        float w0 = W1[i * 31 + c0];
        float w1 = (c0 + 1 < 31) ? W1[i * 31 + c0 + 1] : 0.f;
        float w2 = (c0 + 2 < 31) ? W1[i * 31 + c0 + 2] : 0.f;
        float w3 = (c0 + 3 < 31) ? W1[i * 31 + c0 + 3] : 0.f;
        ulonglong2 pp;
        PACK2(pp.x, w0, w1);
        PACK2(pp.y, w2, w3);
        sW1x[idx] = pp;
        w0 = W2[i * 31 + c0];
        w1 = (c0 + 1 < 31) ? W2[i * 31 + c0 + 1] : 0.f;
        w2 = (c0 + 2 < 31) ? W2[i * 31 + c0 + 2] : 0.f;
        w3 = (c0 + 3 < 31) ? W2[i * 31 + c0 + 3] : 0.f;
        PACK2(pp.x, w0, w1);
        PACK2(pp.y, w2, w3);
        sW2x[idx] = pp;
    }
    if (threadIdx.x < 16) {
        int o = threadIdx.x;
        float lo = b1[2 * o];
        float hi = (2 * o + 1 < 31) ? b1[2 * o + 1] : 0.f;
        u64 p;
        PACK2(p, lo, hi);
        sb1p[o] = p;
        lo = b2[2 * o];
        hi = (2 * o + 1 < 31) ? b2[2 * o + 1] : 0.f;
        PACK2(p, lo, hi);
        sb2p[o] = p;
    }
    if (threadIdx.x < 32) {
        int c = threadIdx.x;
        float sc = 0.f, sf = 0.f;
        if (c < DIM) {
            sc = 1.f;
            if (sumsP) {
                float m = sumsP[c] * invN;
                float var = sumsP[PAD + c] * invN - m * m;
                float istd = rsqrtf(var + BN_EPS);
                sc = gammaP[c] * istd;
                sf = betaP[c] - m * sc;
            }
        }
        ssc[c] = sc;
        ssf[c] = sf;
    }
    __syncthreads();

    int blk = brB ? (blockIdx.x - NPBh) : blockIdx.x;
    int base = blk * 256;
    int off = brB ? N : 0;

    // ---- phase A: coalesced gather + BN affine (incl. deg term) into tile ----
    {
        int gg = threadIdx.x & 7;   // column group (4 floats)
        int sub = threadIdx.x >> 3; // 0..15
        int c0 = gg * 4;
        float sc0 = ssc[c0], sc1 = ssc[c0 + 1], sc2 = ssc[c0 + 2], sc3 = ssc[c0 + 3];
        float sf0 = ssf[c0], sf1 = ssf[c0 + 1], sf2 = ssf[c0 + 2], sf3 = ssf[c0 + 3];
#pragma unroll 1
        for (int pass = 0; pass < 16; pass++) {
            int ln = pass * 16 + sub;
            int lnode = base + ln;
            int n = ((lnode < N) ? lnode : (N - 1)) + off;
            float4 acc = *(const float4*)(yin + (size_t)n * PAD + c0);
            int beg = __ldg(g_rowptr + n), end = __ldg(g_cursor + n);
            int p = beg;
            for (; p + 1 < end; p += 2) {
                int s0 = __ldg(g_perm + p);
                int s1 = __ldg(g_perm + p + 1);
                float4 v0 = *(const float4*)(yin + (size_t)s0 * PAD + c0);
                float4 v1 = *(const float4*)(yin + (size_t)s1 * PAD + c0);
                acc.x += v0.x + v1.x;
                acc.y += v0.y + v1.y;
                acc.z += v0.z + v1.z;
                acc.w += v0.w + v1.w;
            }
            if (p < end) {
                int s0 = __ldg(g_perm + p);
                float4 v0 = *(const float4*)(yin + (size_t)s0 * PAD + c0);
                acc.x += v0.x;
                acc.y += v0.y;
                acc.z += v0.z;
                acc.w += v0.w;
            }
            float dp1 = (float)(end - beg) + 1.f;
            float* hp = hid + ln * RSTR + c0;
            *(float2*)(hp) = make_float2(sc0 * acc.x + dp1 * sf0,
                                         sc1 * acc.y + dp1 * sf1);
            *(float2*)(hp + 2) = make_float2(sc2 * acc.z + dp1 * sf2,
                                             sc3 * acc.w + dp1 * sf3);
        }
    }
    __syncthreads();

    // ---- phase B: EXACT round-9 schedule; thread t owns local nodes 2t, 2t+1 ----
    int t = threadIdx.x;
    int lnA = base + 2 * t, lnB = lnA + 1;
    bool actA = lnA < N, actB = lnB < N;
    int nA = ((actA ? lnA : (N - 1))) + off;
    int nB = ((actB ? lnB : (N - 1))) + off;

    bool doPool = (batchA != nullptr);
    int bA = -1, bB = -1;
    if (doPool) {
        if (actA) bA = brB ? (__ldg(batchB + lnA) + G) : __ldg(batchA + lnA);
        if (actB) bB = brB ? (__ldg(batchB + lnB) + G) : __ldg(batchA + lnB);
    }
    int b0 = __shfl_sync(0xffffffffu, bA, 0);
    bool uniform = doPool && (b0 >= 0) &&
                   __all_sync(0xffffffffu,
                              ((bA == b0) || (bA < 0)) && ((bB == b0) || (bB < 0)));
    int cntAct = __popc(__ballot_sync(0xffffffffu, actA)) +
                 __popc(__ballot_sync(0xffffffffu, actB));

    // bulk-load gathered+BN'd inputs from tile (replaces round-9's global gather)
    u64 ha[16], hb[16];
    {
        const u64* hrA = (const u64*)(hid + (2 * t) * RSTR);
        const u64* hrB = (const u64*)(hid + (2 * t + 1) * RSTR);
#pragma unroll
        for (int k = 0; k < 16; k++) {
            ha[k] = hrA[k];
            hb[k] = hrB[k];
        }
    }

    // ---- layer 1 (shared weight loads feed both nodes) ----
    u64 aA[16], aB[16];
#pragma unroll
    for (int o = 0; o < 16; o++) {
        aA[o] = sb1p[o];
        aB[o] = sb1p[o];
    }
#pragma unroll
    for (int j = 0; j < 16; j++) {
        float xA0, xA1, xB0, xB1;
        UNPACK2(xA0, xA1, ha[j]);
        UNPACK2(xB0, xB1, hb[j]);
        u64 xpA, xpB;
        PACK2(xpA, xA0, xA0);
        PACK2(xpB, xB0, xB0);
        const ulonglong2* wr = sW1x + (2 * j) * 8;
#pragma unroll
        for (int q = 0; q < 8; q++) {
            ulonglong2 wv = wr[q];
            FMA2(aA[2 * q], xpA, wv.x, aA[2 * q]);
            FMA2(aA[2 * q + 1], xpA, wv.y, aA[2 * q + 1]);
            FMA2(aB[2 * q], xpB, wv.x, aB[2 * q]);
            FMA2(aB[2 * q + 1], xpB, wv.y, aB[2 * q + 1]);
        }
        if (j < 15) {
            PACK2(xpA, xA1, xA1);
            PACK2(xpB, xB1, xB1);
            wr = sW1x + (2 * j + 1) * 8;
#pragma unroll
            for (int q = 0; q < 8; q++) {
                ulonglong2 wv = wr[q];
                FMA2(aA[2 * q], xpA, wv.x, aA[2 * q]);
                FMA2(aA[2 * q + 1], xpA, wv.y, aA[2 * q + 1]);
                FMA2(aB[2 * q], xpB, wv.x, aB[2 * q]);
                FMA2(aB[2 * q + 1], xpB, wv.y, aB[2 * q + 1]);
            }
        }
    }
#pragma unroll
    for (int o = 0; o < 16; o++) {
        float lo, hi;
        UNPACK2(lo, hi, aA[o]);
        PACK2(ha[o], fmaxf(lo, 0.f), fmaxf(hi, 0.f));
        UNPACK2(lo, hi, aB[o]);
        PACK2(hb[o], fmaxf(lo, 0.f), fmaxf(hi, 0.f));
    }

    // ---- layer 2 ----
#pragma unroll
    for (int o = 0; o < 16; o++) {
        aA[o] = sb2p[o];
        aB[o] = sb2p[o];
    }
#pragma unroll
    for (int j = 0; j < 16; j++) {
        float xA0, xA1, xB0, xB1;
        UNPACK2(xA0, xA1, ha[j]);
        UNPACK2(xB0, xB1, hb[j]);
        u64 xpA, xpB;
        PACK2(xpA, xA0, xA0);
        PACK2(xpB, xB0, xB0);
        const ulonglong2* wr = sW2x + (2 * j) * 8;
#pragma unroll
        for (int q = 0; q < 8; q++) {
            ulonglong2 wv = wr[q];
            FMA2(aA[2 * q], xpA, wv.x, aA[2 * q]);
            FMA2(aA[2 * q + 1], xpA, wv.y, aA[2 * q + 1]);
            FMA2(aB[2 * q], xpB, wv.x, aB[2 * q]);
            FMA2(aB[2 * q + 1], xpB, wv.y, aB[2 * q + 1]);
        }
        if (j < 15) {
            PACK2(xpA, xA1, xA1);
            PACK2(xpB, xB1, xB1);
            wr = sW2x + (2 * j + 1) * 8;
#pragma unroll
            for (int q = 0; q < 8; q++) {
                ulonglong2 wv = wr[q];
                FMA2(aA[2 * q], xpA, wv.x, aA[2 * q]);
                FMA2(aA[2 * q + 1], xpA, wv.y, aA[2 * q + 1]);
                FMA2(aB[2 * q], xpB, wv.x, aB[2 * q]);
                FMA2(aB[2 * q + 1], xpB, wv.y, aB[2 * q + 1]);
            }
        }
    }

    // ---- relu + mask + store + stats (+pool on layer 4) — round-9 epilogue ----
    int wid = threadIdx.x >> 5, lane = threadIdx.x & 31;
    float amA = actA ? 1.f : 0.f, amB = actB ? 1.f : 0.f;
    float4* outA = (float4*)(yout + (size_t)nA * PAD);
    float4* outB = (float4*)(yout + (size_t)nB * PAD);
    float pA0 = 0.f, pA1 = 0.f, pB0 = 0.f, pB1 = 0.f;
#pragma unroll
    for (int o = 0; o < 16; o++) {
        float loA, hiA, loB, hiB;
        UNPACK2(loA, hiA, aA[o]);
        UNPACK2(loB, hiB, aB[o]);
        loA = fmaxf(loA, 0.f) * amA;
        hiA = fmaxf(hiA, 0.f) * amA;
        loB = fmaxf(loB, 0.f) * amB;
        hiB = fmaxf(hiB, 0.f) * amB;
        if (o == 15) { hiA = 0.f; hiB = 0.f; }
        float s0 = loA + loB, q0 = loA * loA + loB * loB;
        float s1 = hiA + hiB, q1 = hiA * hiA + hiB * hiB;
#pragma unroll
        for (int offX = 16; offX >= 4; offX >>= 1) {
            s0 += __shfl_xor_sync(0xffffffffu, s0, offX);
            q0 += __shfl_xor_sync(0xffffffffu, q0, offX);
            s1 += __shfl_xor_sync(0xffffffffu, s1, offX);
            q1 += __shfl_xor_sync(0xffffffffu, q1, offX);
        }
        if (lane < 4) {
            sstat[(wid * 4 + lane) * 64 + 2 * o + 0] = s0;
            sstat[(wid * 4 + lane) * 64 + 32 + 2 * o + 0] = q0;
            sstat[(wid * 4 + lane) * 64 + 2 * o + 1] = s1;
            sstat[(wid * 4 + lane) * 64 + 32 + 2 * o + 1] = q1;
        }
        if (doPool) {
            if (uniform) {
                s0 += __shfl_xor_sync(0xffffffffu, s0, 2);
                s0 += __shfl_xor_sync(0xffffffffu, s0, 1);
                s1 += __shfl_xor_sync(0xffffffffu, s1, 2);
                s1 += __shfl_xor_sync(0xffffffffu, s1, 1);
                if (lane == 0) {
                    atomicAdd(&g_pooled[(size_t)b0 * PAD + 2 * o], s0);
                    if (2 * o + 1 < DIM)
                        atomicAdd(&g_pooled[(size_t)b0 * PAD + 2 * o + 1], s1);
                }
            } else {
                if (actA) {
                    atomicAdd(&g_pooled[(size_t)bA * PAD + 2 * o], loA);
                    if (2 * o + 1 < DIM)
                        atomicAdd(&g_pooled[(size_t)bA * PAD + 2 * o + 1], hiA);
                }
                if (actB) {
                    atomicAdd(&g_pooled[(size_t)bB * PAD + 2 * o], loB);
                    if (2 * o + 1 < DIM)
                        atomicAdd(&g_pooled[(size_t)bB * PAD + 2 * o + 1], hiB);
                }
            }
        }
        if ((o & 1) == 0) {
            pA0 = loA;
            pA1 = hiA;
            pB0 = loB;
            pB1 = hiB;
        } else {
            if (actA) outA[o >> 1] = make_float4(pA0, pA1, loA, hiA);
            if (actB) outB[o >> 1] = make_float4(pB0, pB1, loB, hiB);
        }
    }
    if (doPool) {
        if (uniform) {
            if (lane == 0) atomicAdd(&g_gcnt[b0], (float)cntAct);
        } else {
            if (actA) atomicAdd(&g_gcnt[bA], 1.f);
            if (actB) atomicAdd(&g_gcnt[bB], 1.f);
        }
    }
    __syncthreads();
    if (threadIdx.x < 64) {
        float tt = 0.f;
#pragma unroll
        for (int r = 0; r < 16; r++) tt += sstat[r * 64 + threadIdx.x];
        partial[(size_t)blockIdx.x * 64 + threadIdx.x] = tt;
    }
}

// ---------------- reduce partials: 128 slots (A:0-63, B:64-127) ----------------
__global__ void k_reduce(float* __restrict__ out, int NPBh) {
    int blk = blockIdx.x;
    int slot = blk & 63;
    int start = (blk >= 64) ? NPBh : 0;
    float s = 0.f;
    for (int i = threadIdx.x; i < NPBh; i += blockDim.x)
        s += g_partial[(size_t)(start + i) * 64 + slot];
#pragma unroll
    for (int o = 16; o > 0; o >>= 1) s += __shfl_xor_sync(0xffffffffu, s, o);
    __shared__ float sh[8];
    if ((threadIdx.x & 31) == 0) sh[threadIdx.x >> 5] = s;
    __syncthreads();
    if (threadIdx.x == 0) {
        float t = 0.f;
#pragma unroll
        for (int w = 0; w < 8; w++) t += sh[w];
        out[blk] = t;
    }
}

// ---------------- per-graph fc with per-branch layer-4 BN affine ----------------
__global__ void k_fcbr(const float* __restrict__ W, const float* __restrict__ bb,
                       const float* __restrict__ gamma4, const float* __restrict__ beta4,
                       float* __restrict__ out, int G, float invN) {
    __shared__ float p[PAD];
    int g = blockIdx.x;
    if (threadIdx.x < PAD) {
        int c = threadIdx.x;
        float val = 0.f;
        if (c < DIM) {
            const float* s = g_sums + 4 * 128 + ((g >= G) ? 64 : 0);
            float m = s[c] * invN;
            float var = s[PAD + c] * invN - m * m;
            float istd = rsqrtf(var + BN_EPS);
            float sc = gamma4[c] * istd;
            float sf = beta4[c] - m * sc;
            val = g_pooled[(size_t)g * PAD + c] * sc + g_gcnt[g] * sf;
        }
        p[c] = val;
    }
    __syncthreads();
    int o = threadIdx.x;
    float acc = __ldg(bb + o);
#pragma unroll
    for (int i = 0; i < DIM; i++) acc += p[i] * __ldg(W + i * 256 + o);
    out[(size_t)g * 256 + o] = fmaxf(acc, 0.f);
}

// ---------------- tiled SGEMM (f32x2): C = act((A [+A2]) @ B + bias) ----------------
template <bool SUM2, bool RELU>
__global__ void k_gemm(const float* __restrict__ A, const float* __restrict__ A2,
                       const float* __restrict__ B, const float* __restrict__ bias,
                       float* __restrict__ C, int M, int N, int K) {
    const int BM = 64, BN = 64, BK = 16;
    __shared__ float As[BM][BK + 1];
    __shared__ float Bs[BK][BN];
    int tx = threadIdx.x % 16, ty = threadIdx.x / 16;
    int row0 = blockIdx.y * BM, col0 = blockIdx.x * BN;
    u64 acc2[4][2];
    u64 zero;
    PACK2(zero, 0.f, 0.f);
#pragma unroll
    for (int u = 0; u < 4; u++) {
        acc2[u][0] = zero;
        acc2[u][1] = zero;
    }
    for (int k0 = 0; k0 < K; k0 += BK) {
        for (int i = threadIdx.x; i < BM * BK; i += 256) {
            int r = i / BK, c = i % BK;
            float v = A[(size_t)(row0 + r) * K + k0 + c];
            if (SUM2) v += A2[(size_t)(row0 + r) * K + k0 + c];
            As[r][c] = v;
        }
        for (int i = threadIdx.x; i < BK * BN; i += 256) {
            int r = i / BN, c = i % BN;
            Bs[r][c] = B[(size_t)(k0 + r) * N + col0 + c];
        }
        __syncthreads();
#pragma unroll
        for (int k = 0; k < BK; k++) {
            u64 b0 = *(const u64*)&Bs[k][tx * 4];
            u64 b1 = *(const u64*)&Bs[k][tx * 4 + 2];
#pragma unroll
            for (int u = 0; u < 4; u++) {
                float a = As[ty * 4 + u][k];
                u64 ap;
                PACK2(ap, a, a);
                FMA2(acc2[u][0], ap, b0, acc2[u][0]);
                FMA2(acc2[u][1], ap, b1, acc2[u][1]);
            }
        }
        __syncthreads();
    }
#pragma unroll
    for (int u = 0; u < 4; u++) {
        int r = row0 + ty * 4 + u;
#pragma unroll
        for (int w = 0; w < 2; w++) {
            float lo, hi;
            UNPACK2(lo, hi, acc2[u][w]);
            int cc = col0 + tx * 4 + 2 * w;
            float v0 = lo + bias[cc];
            float v1 = hi + bias[cc + 1];
            if (RELU) {
                v0 = fmaxf(v0, 0.f);
                v1 = fmaxf(v1, 0.f);
            }
            C[(size_t)r * N + cc] = v0;
            C[(size_t)r * N + cc + 1] = v1;
        }
    }
}

// ---------------- final projection + restore zero-state for next replay ----------------
__global__ void k_out(const float* __restrict__ W, const float* __restrict__ b,
                      float* __restrict__ out, int G, int NN) {
    __shared__ float sW[512];
    for (int i = threadIdx.x; i < 512; i += blockDim.x) sW[i] = W[i];
    __syncthreads();
    int g = blockIdx.x * blockDim.x + threadIdx.x;
    if (g < G) {
        const float4* row = (const float4*)(g_c2 + (size_t)g * 256);
        float a0 = b[0], a1 = b[1];
#pragma unroll 8
        for (int i = 0; i < 64; i++) {
            float4 v = row[i];
            int o = i * 4;
            a0 += v.x * sW[2 * o + 0] + v.y * sW[2 * o + 2] + v.z * sW[2 * o + 4] + v.w * sW[2 * o + 6];
            a1 += v.x * sW[2 * o + 1] + v.y * sW[2 * o + 3] + v.z * sW[2 * o + 5] + v.w * sW[2 * o + 7];
        }
        out[g * 2 + 0] = a0;
        out[g * 2 + 1] = a1;
    }
    int stride = gridDim.x * blockDim.x;
    int tid0 = blockIdx.x * blockDim.x + threadIdx.x;
    for (int t = tid0; t < NN; t += stride) g_cnt[t] = 0;
    for (int t = tid0; t < 2 * GMAX * PAD; t += stride) g_pooled[t] = 0.f;
    for (int t = tid0; t < 2 * GMAX; t += stride) g_gcnt[t] = 0.f;
    if (tid0 == 0) g_total = 0;
}

// ---------------- launch ----------------
extern "C" void kernel_launch(void* const* d_in, const int* in_sizes, int n_in,
                              void* d_out, int out_size) {
    const float* x_a = (const float*)d_in[0];
    const int* ei_a = (const int*)d_in[1];
    const int* batch_a = (const int*)d_in[2];
    const float* x_b = (const float*)d_in[3];
    const int* ei_b = (const int*)d_in[4];
    const int* batch_b = (const int*)d_in[5];
    const float* W1s = (const float*)d_in[6];
    const float* b1s = (const float*)d_in[7];
    const float* W2s = (const float*)d_in[8];
    const float* b2s = (const float*)d_in[9];
    const float* gammas = (const float*)d_in[10];
    const float* betas = (const float*)d_in[11];
    const float* fcxW = (const float*)d_in[12];
    const float* fcxb = (const float*)d_in[13];
    const float* fc1W = (const float*)d_in[14];
    const float* fc1b = (const float*)d_in[15];
    const float* fc2W = (const float*)d_in[16];
    const float* fc2b = (const float*)d_in[17];
    const float* outW = (const float*)d_in[18];
    const float* outb = (const float*)d_in[19];

    int N = in_sizes[0] / DIM;
    int E = in_sizes[1] / 2;
    int G = out_size / 2;
    int NN = 2 * N;
    float invN = 1.f / (float)N;
    int NPBh = (N + 255) / 256;

    float* sums_ptr;
    float* ha_ptr;
    float* c1_ptr;
    float* c2_ptr;
    float* partial_ptr;
    float* y0_ptr;
    float* y1_ptr;
    cudaGetSymbolAddress((void**)&sums_ptr, g_sums);
    cudaGetSymbolAddress((void**)&ha_ptr, g_ha);
    cudaGetSymbolAddress((void**)&c1_ptr, g_c1);
    cudaGetSymbolAddress((void**)&c2_ptr, g_c2);
    cudaGetSymbolAddress((void**)&partial_ptr, g_partial);
    cudaGetSymbolAddress((void**)&y0_ptr, g_y0);
    cudaGetSymbolAddress((void**)&y1_ptr, g_y1);
    float* ybuf[2] = {y0_ptr, y1_ptr};

    k_count<<<2048, 256>>>(ei_a + E, ei_b + E, E, N);
    k_assign<<<(NN + 511) / 512, 512>>>(x_a, x_b, N, NN);
    k_fill<<<2048, 256>>>(ei_a, ei_a + E, ei_b, ei_b + E, E, N);

    for (int l = 0; l < 5; l++) {
        const float* sA = (l == 0) ? nullptr : sums_ptr + (l - 1) * 128;
        const float* sB = (l == 0) ? nullptr : sums_ptr + (l - 1) * 128 + 64;
        const float* gP = (l == 0) ? nullptr : gammas + (l - 1) * DIM;
        const float* bP = (l == 0) ? nullptr : betas + (l - 1) * DIM;
        const int* pA = (l == 4) ? batch_a : nullptr;
        const int* pB = (l == 4) ? batch_b : nullptr;
        k_gmlp<<<2 * NPBh, 128>>>(ybuf[l & 1], ybuf[1 - (l & 1)],
                                  W1s + l * DIM * DIM, b1s + l * DIM,
                                  W2s + l * DIM * DIM, b2s + l * DIM,
                                  gP, bP, sA, sB, partial_ptr, pA, pB,
                                  N, G, NPBh, invN);
        k_reduce<<<128, 256>>>(sums_ptr + l * 128, NPBh);
    }

    k_fcbr<<<2 * G, 256>>>(fcxW, fcxb, gammas + 4 * DIM, betas + 4 * DIM,
                           ha_ptr, G, invN);

    dim3 g1(1024 / 64, G / 64);
    k_gemm<true, true><<<g1, 256>>>(ha_ptr, ha_ptr + (size_t)G * 256, fc1W, fc1b,
                                    c1_ptr, G, 1024, 256);
    dim3 g2(256 / 64, G / 64);
    k_gemm<false, true><<<g2, 256>>>(c1_ptr, nullptr, fc2W, fc2b, c2_ptr, G, 256, 1024);
    k_out<<<1024, 256>>>(outW, outb, (float*)d_out, G, NN);
}

// round 15
// speedup vs baseline: 5.0984x; 1.3774x over previous
#include <cuda_runtime.h>

#define DIM 31
#define PAD 32
#define NMAX 500000
#define EMAX 2000000
#define GMAX 4096
#define BN_EPS 1e-5f

typedef unsigned long long u64;

#define PACK2(d, lo, hi) \
    asm("mov.b64 %0, {%1, %2};" : "=l"(d) : "r"(__float_as_uint(lo)), "r"(__float_as_uint(hi)))
#define UNPACK2(lo, hi, s)                                  \
    do {                                                    \
        unsigned _l, _h;                                    \
        asm("mov.b64 {%0, %1}, %2;" : "=r"(_l), "=r"(_h) : "l"(s)); \
        lo = __uint_as_float(_l);                           \
        hi = __uint_as_float(_h);                           \
    } while (0)
#define FMA2(d, a, b, c) \
    asm("fma.rn.f32x2 %0, %1, %2, %3;" : "=l"(d) : "l"(a), "l"(b), "l"(c))
#define ADD2(d, a, b) \
    asm("add.rn.f32x2 %0, %1, %2;" : "=l"(d) : "l"(a), "l"(b))
#define MUL2(d, a, b) \
    asm("mul.rn.f32x2 %0, %1, %2;" : "=l"(d) : "l"(a), "l"(b))

// ---------------- scratch (both branches concatenated: 2N nodes) ----------------
// State contract: g_cnt, g_pooled, g_gcnt, g_total, g_sums are ZERO at entry
// (zero-init at load; re-zeroed by k_out each run).
__device__ float g_y0[(size_t)2 * NMAX * PAD];
__device__ float g_y1[(size_t)2 * NMAX * PAD];
__device__ int   g_cnt[2 * NMAX];
__device__ int   g_rowptr[2 * NMAX];
__device__ int   g_cursor[2 * NMAX];          // after k_fill: == segment end
__device__ int   g_perm[2 * EMAX];
__device__ int   g_total;
__device__ float g_sums[5 * 128];             // per layer: [A sum32|A sumsq32|B sum32|B sumsq32]
__device__ float g_pooled[2 * GMAX * PAD];
__device__ float g_gcnt[2 * GMAX];
__device__ float g_ha[(size_t)2 * GMAX * 256];
__device__ float g_c1[(size_t)GMAX * 1024];
__device__ float g_c2[GMAX * 256];

// ---------------- count in-degree (g_cnt pre-zeroed) ----------------
__global__ void k_count(const int* __restrict__ dsta, const int* __restrict__ dstb,
                        int E, int N) {
    for (int e = blockIdx.x * blockDim.x + threadIdx.x; e < 2 * E;
         e += gridDim.x * blockDim.x) {
        int d = (e < E) ? __ldg(dsta + e) : (__ldg(dstb + e - E) + N);
        atomicAdd(&g_cnt[d], 1);
    }
}

// ---------------- scan-free segment assignment + pack x into y0 ----------------
__global__ void k_assign(const float* __restrict__ xa, const float* __restrict__ xb,
                         int N, int NN) {
    __shared__ int s[512];
    __shared__ int sbase;
    int i = blockIdx.x * 512 + threadIdx.x;
    int c = (i < NN) ? g_cnt[i] : 0;
    s[threadIdx.x] = c;
    __syncthreads();
    for (int o = 1; o < 512; o <<= 1) {
        int t = (threadIdx.x >= o) ? s[threadIdx.x - o] : 0;
        __syncthreads();
        s[threadIdx.x] += t;
        __syncthreads();
    }
    if (threadIdx.x == 511) sbase = atomicAdd(&g_total, s[511]);
    __syncthreads();
    int ex = s[threadIdx.x] - c + sbase;
    if (i < NN) {
        g_rowptr[i] = ex;
        g_cursor[i] = ex;
    }
    int stride = gridDim.x * blockDim.x;
    int tid0 = blockIdx.x * blockDim.x + threadIdx.x;
    int total = N * PAD;
    for (int t = tid0; t < total; t += stride) {
        int cc = t & (PAD - 1);
        int ii = t >> 5;
        g_y0[t] = (cc < DIM) ? xa[ii * DIM + cc] : 0.f;
        g_y0[(size_t)N * PAD + t] = (cc < DIM) ? xb[ii * DIM + cc] : 0.f;
    }
}

// ---------------- fill CSR (g_cursor -> segment ends) ----------------
__global__ void k_fill(const int* __restrict__ srca, const int* __restrict__ dsta,
                       const int* __restrict__ srcb, const int* __restrict__ dstb,
                       int E, int N) {
    for (int e = blockIdx.x * blockDim.x + threadIdx.x; e < 2 * E;
         e += gridDim.x * blockDim.x) {
        int d, s;
        if (e < E) {
            d = __ldg(dsta + e);
            s = __ldg(srca + e);
        } else {
            d = __ldg(dstb + e - E) + N;
            s = __ldg(srcb + e - E) + N;
        }
        int p = atomicAdd(&g_cursor[d], 1);
        g_perm[p] = s;
    }
}

// ---------------- fused gather + BN affine + MLP + stats + pool, 2 nodes/thread ----------------
__global__ void __launch_bounds__(128, 3)
k_gmlp(const float* __restrict__ yin, float* __restrict__ yout,
       const float* __restrict__ W1, const float* __restrict__ b1,
       const float* __restrict__ W2, const float* __restrict__ b2,
       const float* __restrict__ gammaP, const float* __restrict__ betaP,
       const float* __restrict__ sumsPA, const float* __restrict__ sumsPB,
       float* __restrict__ sumsC,
       const int* __restrict__ batchA, const int* __restrict__ batchB,
       int N, int G, int NPBh, float invN) {
    __shared__ ulonglong2 sW1x[31 * 8], sW2x[31 * 8];
    __shared__ u64 sb1p[16], sb2p[16];
    __shared__ float ssc[32], ssf[32];
    __shared__ u64 ssc2[16], ssf2[16];
    __shared__ float sstat[16 * 64];

    bool brB = blockIdx.x >= NPBh;
    const float* sumsP = brB ? sumsPB : sumsPA;

    for (int idx = threadIdx.x; idx < 31 * 8; idx += 128) {
        int i = idx >> 3, q = idx & 7;
        int c0 = 4 * q;
        float w0 = W1[i * 31 + c0];
        float w1 = (c0 + 1 < 31) ? W1[i * 31 + c0 + 1] : 0.f;
        float w2 = (c0 + 2 < 31) ? W1[i * 31 + c0 + 2] : 0.f;
        float w3 = (c0 + 3 < 31) ? W1[i * 31 + c0 + 3] : 0.f;
        ulonglong2 pp;
        PACK2(pp.x, w0, w1);
        PACK2(pp.y, w2, w3);
        sW1x[idx] = pp;
        w0 = W2[i * 31 + c0];
        w1 = (c0 + 1 < 31) ? W2[i * 31 + c0 + 1] : 0.f;
        w2 = (c0 + 2 < 31) ? W2[i * 31 + c0 + 2] : 0.f;
        w3 = (c0 + 3 < 31) ? W2[i * 31 + c0 + 3] : 0.f;
        PACK2(pp.x, w0, w1);
        PACK2(pp.y, w2, w3);
        sW2x[idx] = pp;
    }
    if (threadIdx.x < 16) {
        int o = threadIdx.x;
        float lo = b1[2 * o];
        float hi = (2 * o + 1 < 31) ? b1[2 * o + 1] : 0.f;
        u64 p;
        PACK2(p, lo, hi);
        sb1p[o] = p;
        lo = b2[2 * o];
        hi = (2 * o + 1 < 31) ? b2[2 * o + 1] : 0.f;
        PACK2(p, lo, hi);
        sb2p[o] = p;
    }
    if (threadIdx.x < 32) {
        int c = threadIdx.x;
        float sc = 0.f, sf = 0.f;
        if (c < DIM) {
            sc = 1.f;
            if (sumsP) {
                float m = sumsP[c] * invN;
                float var = sumsP[PAD + c] * invN - m * m;
                float istd = rsqrtf(var + BN_EPS);
                sc = gammaP[c] * istd;
                sf = betaP[c] - m * sc;
            }
        }
        ssc[c] = sc;
        ssf[c] = sf;
    }
    __syncthreads();
    if (threadIdx.x < 16) {
        int j = threadIdx.x;
        u64 p;
        PACK2(p, ssc[2 * j], ssc[2 * j + 1]);
        ssc2[j] = p;
        PACK2(p, ssf[2 * j], ssf[2 * j + 1]);
        ssf2[j] = p;
    }
    __syncthreads();

    int blk = brB ? (blockIdx.x - NPBh) : blockIdx.x;
    int lnA = blk * 256 + 2 * threadIdx.x;
    int lnB = lnA + 1;
    bool actA = lnA < N, actB = lnB < N;
    int off = brB ? N : 0;
    int nA = (actA ? lnA : (N - 1)) + off;
    int nB = (actB ? lnB : (N - 1)) + off;

    bool doPool = (batchA != nullptr);
    int bA = -1, bB = -1;
    if (doPool) {
        if (actA) bA = brB ? (__ldg(batchB + lnA) + G) : __ldg(batchA + lnA);
        if (actB) bB = brB ? (__ldg(batchB + lnB) + G) : __ldg(batchA + lnB);
    }
    int b0 = __shfl_sync(0xffffffffu, bA, 0);
    bool uniform = doPool && (b0 >= 0) &&
                   __all_sync(0xffffffffu,
                              ((bA == b0) || (bA < 0)) && ((bB == b0) || (bB < 0)));
    int cntAct = __popc(__ballot_sync(0xffffffffu, actA)) +
                 __popc(__ballot_sync(0xffffffffu, actB));

    // ---- gather both nodes ----
    u64 ha[16], hb[16];
    {
        const ulonglong2* sr = (const ulonglong2*)(yin + (size_t)nA * PAD);
#pragma unroll
        for (int q = 0; q < 8; q++) {
            ulonglong2 v = sr[q];
            ha[2 * q] = v.x;
            ha[2 * q + 1] = v.y;
        }
        sr = (const ulonglong2*)(yin + (size_t)nB * PAD);
#pragma unroll
        for (int q = 0; q < 8; q++) {
            ulonglong2 v = sr[q];
            hb[2 * q] = v.x;
            hb[2 * q + 1] = v.y;
        }
    }
    int begA = __ldg(g_rowptr + nA), endA = __ldg(g_cursor + nA);
    int begB = __ldg(g_rowptr + nB), endB = __ldg(g_cursor + nB);
    int degA = endA - begA, degB = endB - begB;
    {
        int p = begA;
        for (; p + 1 < endA; p += 2) {
            int s0 = __ldg(g_perm + p);
            int s1 = __ldg(g_perm + p + 1);
            const ulonglong2* r0 = (const ulonglong2*)(yin + (size_t)s0 * PAD);
            const ulonglong2* r1 = (const ulonglong2*)(yin + (size_t)s1 * PAD);
#pragma unroll
            for (int q = 0; q < 8; q++) {
                ulonglong2 v0 = r0[q];
                ulonglong2 v1 = r1[q];
                ADD2(ha[2 * q], ha[2 * q], v0.x);
                ADD2(ha[2 * q + 1], ha[2 * q + 1], v0.y);
                ADD2(ha[2 * q], ha[2 * q], v1.x);
                ADD2(ha[2 * q + 1], ha[2 * q + 1], v1.y);
            }
        }
        if (p < endA) {
            int s0 = __ldg(g_perm + p);
            const ulonglong2* r0 = (const ulonglong2*)(yin + (size_t)s0 * PAD);
#pragma unroll
            for (int q = 0; q < 8; q++) {
                ulonglong2 v0 = r0[q];
                ADD2(ha[2 * q], ha[2 * q], v0.x);
                ADD2(ha[2 * q + 1], ha[2 * q + 1], v0.y);
            }
        }
        p = begB;
        for (; p + 1 < endB; p += 2) {
            int s0 = __ldg(g_perm + p);
            int s1 = __ldg(g_perm + p + 1);
            const ulonglong2* r0 = (const ulonglong2*)(yin + (size_t)s0 * PAD);
            const ulonglong2* r1 = (const ulonglong2*)(yin + (size_t)s1 * PAD);
#pragma unroll
            for (int q = 0; q < 8; q++) {
                ulonglong2 v0 = r0[q];
                ulonglong2 v1 = r1[q];
                ADD2(hb[2 * q], hb[2 * q], v0.x);
                ADD2(hb[2 * q + 1], hb[2 * q + 1], v0.y);
                ADD2(hb[2 * q], hb[2 * q], v1.x);
                ADD2(hb[2 * q + 1], hb[2 * q + 1], v1.y);
            }
        }
        if (p < endB) {
            int s0 = __ldg(g_perm + p);
            const ulonglong2* r0 = (const ulonglong2*)(yin + (size_t)s0 * PAD);
#pragma unroll
            for (int q = 0; q < 8; q++) {
                ulonglong2 v0 = r0[q];
                ADD2(hb[2 * q], hb[2 * q], v0.x);
                ADD2(hb[2 * q + 1], hb[2 * q + 1], v0.y);
            }
        }
    }

    // ---- BN affine (packed) ----
    {
        float dA = (float)degA + 1.f, dB = (float)degB + 1.f;
        u64 dpA, dpB;
        PACK2(dpA, dA, dA);
        PACK2(dpB, dB, dB);
#pragma unroll
        for (int j = 0; j < 16; j++) {
            u64 t;
            MUL2(t, dpA, ssf2[j]);
            FMA2(ha[j], ha[j], ssc2[j], t);
            MUL2(t, dpB, ssf2[j]);
            FMA2(hb[j], hb[j], ssc2[j], t);
        }
    }

    // ---- layer 1 (shared weight loads feed both nodes) ----
    u64 aA[16], aB[16];
#pragma unroll
    for (int o = 0; o < 16; o++) {
        aA[o] = sb1p[o];
        aB[o] = sb1p[o];
    }
#pragma unroll
    for (int j = 0; j < 16; j++) {
        float xA0, xA1, xB0, xB1;
        UNPACK2(xA0, xA1, ha[j]);
        UNPACK2(xB0, xB1, hb[j]);
        u64 xpA, xpB;
        PACK2(xpA, xA0, xA0);
        PACK2(xpB, xB0, xB0);
        const ulonglong2* wr = sW1x + (2 * j) * 8;
#pragma unroll
        for (int q = 0; q < 8; q++) {
            ulonglong2 wv = wr[q];
            FMA2(aA[2 * q], xpA, wv.x, aA[2 * q]);
            FMA2(aA[2 * q + 1], xpA, wv.y, aA[2 * q + 1]);
            FMA2(aB[2 * q], xpB, wv.x, aB[2 * q]);
            FMA2(aB[2 * q + 1], xpB, wv.y, aB[2 * q + 1]);
        }
        if (j < 15) {
            PACK2(xpA, xA1, xA1);
            PACK2(xpB, xB1, xB1);
            wr = sW1x + (2 * j + 1) * 8;
#pragma unroll
            for (int q = 0; q < 8; q++) {
                ulonglong2 wv = wr[q];
                FMA2(aA[2 * q], xpA, wv.x, aA[2 * q]);
                FMA2(aA[2 * q + 1], xpA, wv.y, aA[2 * q + 1]);
                FMA2(aB[2 * q], xpB, wv.x, aB[2 * q]);
                FMA2(aB[2 * q + 1], xpB, wv.y, aB[2 * q + 1]);
            }
        }
    }
#pragma unroll
    for (int o = 0; o < 16; o++) {
        float lo, hi;
        UNPACK2(lo, hi, aA[o]);
        PACK2(ha[o], fmaxf(lo, 0.f), fmaxf(hi, 0.f));
        UNPACK2(lo, hi, aB[o]);
        PACK2(hb[o], fmaxf(lo, 0.f), fmaxf(hi, 0.f));
    }

    // ---- layer 2 ----
#pragma unroll
    for (int o = 0; o < 16; o++) {
        aA[o] = sb2p[o];
        aB[o] = sb2p[o];
    }
#pragma unroll
    for (int j = 0; j < 16; j++) {
        float xA0, xA1, xB0, xB1;
        UNPACK2(xA0, xA1, ha[j]);
        UNPACK2(xB0, xB1, hb[j]);
        u64 xpA, xpB;
        PACK2(xpA, xA0, xA0);
        PACK2(xpB, xB0, xB0);
        const ulonglong2* wr = sW2x + (2 * j) * 8;
#pragma unroll
        for (int q = 0; q < 8; q++) {
            ulonglong2 wv = wr[q];
            FMA2(aA[2 * q], xpA, wv.x, aA[2 * q]);
            FMA2(aA[2 * q + 1], xpA, wv.y, aA[2 * q + 1]);
            FMA2(aB[2 * q], xpB, wv.x, aB[2 * q]);
            FMA2(aB[2 * q + 1], xpB, wv.y, aB[2 * q + 1]);
        }
        if (j < 15) {
            PACK2(xpA, xA1, xA1);
            PACK2(xpB, xB1, xB1);
            wr = sW2x + (2 * j + 1) * 8;
#pragma unroll
            for (int q = 0; q < 8; q++) {
                ulonglong2 wv = wr[q];
                FMA2(aA[2 * q], xpA, wv.x, aA[2 * q]);
                FMA2(aA[2 * q + 1], xpA, wv.y, aA[2 * q + 1]);
                FMA2(aB[2 * q], xpB, wv.x, aB[2 * q]);
                FMA2(aB[2 * q + 1], xpB, wv.y, aB[2 * q + 1]);
            }
        }
    }

    // ---- relu + mask + store + stats (+pool on layer 4) ----
    int wid = threadIdx.x >> 5, lane = threadIdx.x & 31;
    float amA = actA ? 1.f : 0.f, amB = actB ? 1.f : 0.f;
    float4* outA = (float4*)(yout + (size_t)nA * PAD);
    float4* outB = (float4*)(yout + (size_t)nB * PAD);
    float pA0 = 0.f, pA1 = 0.f, pB0 = 0.f, pB1 = 0.f;
#pragma unroll
    for (int o = 0; o < 16; o++) {
        float loA, hiA, loB, hiB;
        UNPACK2(loA, hiA, aA[o]);
        UNPACK2(loB, hiB, aB[o]);
        loA = fmaxf(loA, 0.f) * amA;
        hiA = fmaxf(hiA, 0.f) * amA;
        loB = fmaxf(loB, 0.f) * amB;
        hiB = fmaxf(hiB, 0.f) * amB;
        if (o == 15) { hiA = 0.f; hiB = 0.f; }  // col 31 padding
        float s0 = loA + loB, q0 = loA * loA + loB * loB;
        float s1 = hiA + hiB, q1 = hiA * hiA + hiB * hiB;
#pragma unroll
        for (int offX = 16; offX >= 4; offX >>= 1) {
            s0 += __shfl_xor_sync(0xffffffffu, s0, offX);
            q0 += __shfl_xor_sync(0xffffffffu, q0, offX);
            s1 += __shfl_xor_sync(0xffffffffu, s1, offX);
            q1 += __shfl_xor_sync(0xffffffffu, q1, offX);
        }
        if (lane < 4) {
            sstat[(wid * 4 + lane) * 64 + 2 * o + 0] = s0;
            sstat[(wid * 4 + lane) * 64 + 32 + 2 * o + 0] = q0;
            sstat[(wid * 4 + lane) * 64 + 2 * o + 1] = s1;
            sstat[(wid * 4 + lane) * 64 + 32 + 2 * o + 1] = q1;
        }
        if (doPool) {
            if (uniform) {
                s0 += __shfl_xor_sync(0xffffffffu, s0, 2);
                s0 += __shfl_xor_sync(0xffffffffu, s0, 1);
                s1 += __shfl_xor_sync(0xffffffffu, s1, 2);
                s1 += __shfl_xor_sync(0xffffffffu, s1, 1);
                if (lane == 0) {
                    atomicAdd(&g_pooled[(size_t)b0 * PAD + 2 * o], s0);
                    if (2 * o + 1 < DIM)
                        atomicAdd(&g_pooled[(size_t)b0 * PAD + 2 * o + 1], s1);
                }
            } else {
                if (actA) {
                    atomicAdd(&g_pooled[(size_t)bA * PAD + 2 * o], loA);
                    if (2 * o + 1 < DIM)
                        atomicAdd(&g_pooled[(size_t)bA * PAD + 2 * o + 1], hiA);
                }
                if (actB) {
                    atomicAdd(&g_pooled[(size_t)bB * PAD + 2 * o], loB);
                    if (2 * o + 1 < DIM)
                        atomicAdd(&g_pooled[(size_t)bB * PAD + 2 * o + 1], hiB);
                }
            }
        }
        if ((o & 1) == 0) {
            pA0 = loA;
            pA1 = hiA;
            pB0 = loB;
            pB1 = hiB;
        } else {
            if (actA) outA[o >> 1] = make_float4(pA0, pA1, loA, hiA);
            if (actB) outB[o >> 1] = make_float4(pB0, pB1, loB, hiB);
        }
    }
    if (doPool) {
        if (uniform) {
            if (lane == 0) atomicAdd(&g_gcnt[b0], (float)cntAct);
        } else {
            if (actA) atomicAdd(&g_gcnt[bA], 1.f);
            if (actB) atomicAdd(&g_gcnt[bB], 1.f);
        }
    }
    __syncthreads();
    // per-block 64 partials -> direct global accumulation (replaces k_reduce)
    if (threadIdx.x < 64) {
        float t = 0.f;
#pragma unroll
        for (int r = 0; r < 16; r++) t += sstat[r * 64 + threadIdx.x];
        atomicAdd(&sumsC[(brB ? 64 : 0) + threadIdx.x], t);
    }
}

// ---------------- per-graph fc with per-branch layer-4 BN affine ----------------
__global__ void k_fcbr(const float* __restrict__ W, const float* __restrict__ bb,
                       const float* __restrict__ gamma4, const float* __restrict__ beta4,
                       float* __restrict__ out, int G, float invN) {
    __shared__ float p[PAD];
    int g = blockIdx.x;  // 0..2G-1
    if (threadIdx.x < PAD) {
        int c = threadIdx.x;
        float val = 0.f;
        if (c < DIM) {
            const float* s = g_sums + 4 * 128 + ((g >= G) ? 64 : 0);
            float m = s[c] * invN;
            float var = s[PAD + c] * invN - m * m;
            float istd = rsqrtf(var + BN_EPS);
            float sc = gamma4[c] * istd;
            float sf = beta4[c] - m * sc;
            val = g_pooled[(size_t)g * PAD + c] * sc + g_gcnt[g] * sf;
        }
        p[c] = val;
    }
    __syncthreads();
    int o = threadIdx.x;
    float acc = __ldg(bb + o);
#pragma unroll
    for (int i = 0; i < DIM; i++) acc += p[i] * __ldg(W + i * 256 + o);
    out[(size_t)g * 256 + o] = fmaxf(acc, 0.f);
}

// ---------------- tiled SGEMM (f32x2): C = act((A [+A2]) @ B + bias) ----------------
template <bool SUM2, bool RELU>
__global__ void k_gemm(const float* __restrict__ A, const float* __restrict__ A2,
                       const float* __restrict__ B, const float* __restrict__ bias,
                       float* __restrict__ C, int M, int N, int K) {
    const int BM = 64, BN = 64, BK = 16;
    __shared__ float As[BM][BK + 1];
    __shared__ float Bs[BK][BN];
    int tx = threadIdx.x % 16, ty = threadIdx.x / 16;
    int row0 = blockIdx.y * BM, col0 = blockIdx.x * BN;
    u64 acc2[4][2];
    u64 zero;
    PACK2(zero, 0.f, 0.f);
#pragma unroll
    for (int u = 0; u < 4; u++) {
        acc2[u][0] = zero;
        acc2[u][1] = zero;
    }
    for (int k0 = 0; k0 < K; k0 += BK) {
        for (int i = threadIdx.x; i < BM * BK; i += 256) {
            int r = i / BK, c = i % BK;
            float v = A[(size_t)(row0 + r) * K + k0 + c];
            if (SUM2) v += A2[(size_t)(row0 + r) * K + k0 + c];
            As[r][c] = v;
        }
        for (int i = threadIdx.x; i < BK * BN; i += 256) {
            int r = i / BN, c = i % BN;
            Bs[r][c] = B[(size_t)(k0 + r) * N + col0 + c];
        }
        __syncthreads();
#pragma unroll
        for (int k = 0; k < BK; k++) {
            u64 b0 = *(const u64*)&Bs[k][tx * 4];
            u64 b1 = *(const u64*)&Bs[k][tx * 4 + 2];
#pragma unroll
            for (int u = 0; u < 4; u++) {
                float a = As[ty * 4 + u][k];
                u64 ap;
                PACK2(ap, a, a);
                FMA2(acc2[u][0], ap, b0, acc2[u][0]);
                FMA2(acc2[u][1], ap, b1, acc2[u][1]);
            }
        }
        __syncthreads();
    }
#pragma unroll
    for (int u = 0; u < 4; u++) {
        int r = row0 + ty * 4 + u;
#pragma unroll
        for (int w = 0; w < 2; w++) {
            float lo, hi;
            UNPACK2(lo, hi, acc2[u][w]);
            int cc = col0 + tx * 4 + 2 * w;
            float v0 = lo + bias[cc];
            float v1 = hi + bias[cc + 1];
            if (RELU) {
                v0 = fmaxf(v0, 0.f);
                v1 = fmaxf(v1, 0.f);
            }
            C[(size_t)r * N + cc] = v0;
            C[(size_t)r * N + cc + 1] = v1;
        }
    }
}

// ---------------- final projection + restore zero-state for next replay ----------------
__global__ void k_out(const float* __restrict__ W, const float* __restrict__ b,
                      float* __restrict__ out, int G, int NN) {
    __shared__ float sW[512];
    for (int i = threadIdx.x; i < 512; i += blockDim.x) sW[i] = W[i];
    __syncthreads();
    int g = blockIdx.x * blockDim.x + threadIdx.x;
    if (g < G) {
        const float4* row = (const float4*)(g_c2 + (size_t)g * 256);
        float a0 = b[0], a1 = b[1];
#pragma unroll 8
        for (int i = 0; i < 64; i++) {
            float4 v = row[i];
            int o = i * 4;
            a0 += v.x * sW[2 * o + 0] + v.y * sW[2 * o + 2] + v.z * sW[2 * o + 4] + v.w * sW[2 * o + 6];
            a1 += v.x * sW[2 * o + 1] + v.y * sW[2 * o + 3] + v.z * sW[2 * o + 5] + v.w * sW[2 * o + 7];
        }
        out[g * 2 + 0] = a0;
        out[g * 2 + 1] = a1;
    }
    // restore zero state (consumed-and-reset invariant)
    int stride = gridDim.x * blockDim.x;
    int tid0 = blockIdx.x * blockDim.x + threadIdx.x;
    for (int t = tid0; t < NN; t += stride) g_cnt[t] = 0;
    for (int t = tid0; t < 2 * GMAX * PAD; t += stride) g_pooled[t] = 0.f;
    for (int t = tid0; t < 2 * GMAX; t += stride) g_gcnt[t] = 0.f;
    for (int t = tid0; t < 5 * 128; t += stride) g_sums[t] = 0.f;
    if (tid0 == 0) g_total = 0;
}

// ---------------- launch ----------------
extern "C" void kernel_launch(void* const* d_in, const int* in_sizes, int n_in,
                              void* d_out, int out_size) {
    const float* x_a = (const float*)d_in[0];
    const int* ei_a = (const int*)d_in[1];
    const int* batch_a = (const int*)d_in[2];
    const float* x_b = (const float*)d_in[3];
    const int* ei_b = (const int*)d_in[4];
    const int* batch_b = (const int*)d_in[5];
    const float* W1s = (const float*)d_in[6];
    const float* b1s = (const float*)d_in[7];
    const float* W2s = (const float*)d_in[8];
    const float* b2s = (const float*)d_in[9];
    const float* gammas = (const float*)d_in[10];
    const float* betas = (const float*)d_in[11];
    const float* fcxW = (const float*)d_in[12];
    const float* fcxb = (const float*)d_in[13];
    const float* fc1W = (const float*)d_in[14];
    const float* fc1b = (const float*)d_in[15];
    const float* fc2W = (const float*)d_in[16];
    const float* fc2b = (const float*)d_in[17];
    const float* outW = (const float*)d_in[18];
    const float* outb = (const float*)d_in[19];

    int N = in_sizes[0] / DIM;
    int E = in_sizes[1] / 2;
    int G = out_size / 2;
    int NN = 2 * N;
    float invN = 1.f / (float)N;
    int NPBh = (N + 255) / 256;  // 256 nodes per block (2/thread)

    float* sums_ptr;
    float* ha_ptr;
    float* c1_ptr;
    float* c2_ptr;
    float* y0_ptr;
    float* y1_ptr;
    cudaGetSymbolAddress((void**)&sums_ptr, g_sums);
    cudaGetSymbolAddress((void**)&ha_ptr, g_ha);
    cudaGetSymbolAddress((void**)&c1_ptr, g_c1);
    cudaGetSymbolAddress((void**)&c2_ptr, g_c2);
    cudaGetSymbolAddress((void**)&y0_ptr, g_y0);
    cudaGetSymbolAddress((void**)&y1_ptr, g_y1);
    float* ybuf[2] = {y0_ptr, y1_ptr};

    k_count<<<2048, 256>>>(ei_a + E, ei_b + E, E, N);
    k_assign<<<(NN + 511) / 512, 512>>>(x_a, x_b, N, NN);
    k_fill<<<2048, 256>>>(ei_a, ei_a + E, ei_b, ei_b + E, E, N);

    for (int l = 0; l < 5; l++) {
        const float* sA = (l == 0) ? nullptr : sums_ptr + (l - 1) * 128;
        const float* sB = (l == 0) ? nullptr : sums_ptr + (l - 1) * 128 + 64;
        const float* gP = (l == 0) ? nullptr : gammas + (l - 1) * DIM;
        const float* bP = (l == 0) ? nullptr : betas + (l - 1) * DIM;
        const int* pA = (l == 4) ? batch_a : nullptr;
        const int* pB = (l == 4) ? batch_b : nullptr;
        k_gmlp<<<2 * NPBh, 128>>>(ybuf[l & 1], ybuf[1 - (l & 1)],
                                  W1s + l * DIM * DIM, b1s + l * DIM,
                                  W2s + l * DIM * DIM, b2s + l * DIM,
                                  gP, bP, sA, sB, sums_ptr + l * 128, pA, pB,
                                  N, G, NPBh, invN);
    }

    k_fcbr<<<2 * G, 256>>>(fcxW, fcxb, gammas + 4 * DIM, betas + 4 * DIM,
                           ha_ptr, G, invN);

    dim3 g1(1024 / 64, G / 64);
    k_gemm<true, true><<<g1, 256>>>(ha_ptr, ha_ptr + (size_t)G * 256, fc1W, fc1b,
                                    c1_ptr, G, 1024, 256);
    dim3 g2(256 / 64, G / 64);
    k_gemm<false, true><<<g2, 256>>>(c1_ptr, nullptr, fc2W, fc2b, c2_ptr, G, 256, 1024);
    k_out<<<1024, 256>>>(outW, outb, (float*)d_out, G, NN);
}

// round 16
// speedup vs baseline: 5.6761x; 1.1133x over previous
#include <cuda_runtime.h>

#define DIM 31
#define PAD 32
#define NMAX 500000
#define EMAX 2000000
#define GMAX 4096
#define BN_EPS 1e-5f

typedef unsigned long long u64;

#define PACK2(d, lo, hi) \
    asm("mov.b64 %0, {%1, %2};" : "=l"(d) : "r"(__float_as_uint(lo)), "r"(__float_as_uint(hi)))
#define UNPACK2(lo, hi, s)                                  \
    do {                                                    \
        unsigned _l, _h;                                    \
        asm("mov.b64 {%0, %1}, %2;" : "=r"(_l), "=r"(_h) : "l"(s)); \
        lo = __uint_as_float(_l);                           \
        hi = __uint_as_float(_h);                           \
    } while (0)
#define FMA2(d, a, b, c) \
    asm("fma.rn.f32x2 %0, %1, %2, %3;" : "=l"(d) : "l"(a), "l"(b), "l"(c))

// ---------------- scratch (both branches concatenated: 2N nodes) ----------------
// State contract: g_cnt, g_pooled, g_gcnt, g_total, g_sums are ZERO at entry
// (zero-init at load; re-zeroed by k_out each run).
__device__ float g_y[(size_t)2 * NMAX * PAD];  // node features
__device__ float g_h[(size_t)2 * NMAX * PAD];  // gathered + BN-affine'd MLP inputs
__device__ int   g_cnt[2 * NMAX];
__device__ int   g_rowptr[2 * NMAX];
__device__ int   g_cursor[2 * NMAX];          // after k_fill: == segment end
__device__ int   g_perm[2 * EMAX];
__device__ int   g_total;
__device__ float g_sums[5 * 128];             // per layer: [A sum32|A sumsq32|B sum32|B sumsq32]
__device__ float g_pooled[2 * GMAX * PAD];
__device__ float g_gcnt[2 * GMAX];
__device__ float g_ha[(size_t)2 * GMAX * 256];
__device__ float g_c1[(size_t)GMAX * 1024];
__device__ float g_c2[GMAX * 256];

// ---------------- count in-degree (g_cnt pre-zeroed) ----------------
__global__ void k_count(const int* __restrict__ dsta, const int* __restrict__ dstb,
                        int E, int N) {
    for (int e = blockIdx.x * blockDim.x + threadIdx.x; e < 2 * E;
         e += gridDim.x * blockDim.x) {
        int d = (e < E) ? __ldg(dsta + e) : (__ldg(dstb + e - E) + N);
        atomicAdd(&g_cnt[d], 1);
    }
}

// ---------------- scan-free segment assignment + pack x into y ----------------
__global__ void k_assign(const float* __restrict__ xa, const float* __restrict__ xb,
                         int N, int NN) {
    __shared__ int s[512];
    __shared__ int sbase;
    int i = blockIdx.x * 512 + threadIdx.x;
    int c = (i < NN) ? g_cnt[i] : 0;
    s[threadIdx.x] = c;
    __syncthreads();
    for (int o = 1; o < 512; o <<= 1) {
        int t = (threadIdx.x >= o) ? s[threadIdx.x - o] : 0;
        __syncthreads();
        s[threadIdx.x] += t;
        __syncthreads();
    }
    if (threadIdx.x == 511) sbase = atomicAdd(&g_total, s[511]);
    __syncthreads();
    int ex = s[threadIdx.x] - c + sbase;
    if (i < NN) {
        g_rowptr[i] = ex;
        g_cursor[i] = ex;
    }
    int stride = gridDim.x * blockDim.x;
    int tid0 = blockIdx.x * blockDim.x + threadIdx.x;
    int total = N * PAD;
    for (int t = tid0; t < total; t += stride) {
        int cc = t & (PAD - 1);
        int ii = t >> 5;
        g_y[t] = (cc < DIM) ? xa[ii * DIM + cc] : 0.f;
        g_y[(size_t)N * PAD + t] = (cc < DIM) ? xb[ii * DIM + cc] : 0.f;
    }
}

// ---------------- fill CSR (g_cursor -> segment ends) ----------------
__global__ void k_fill(const int* __restrict__ srca, const int* __restrict__ dsta,
                       const int* __restrict__ srcb, const int* __restrict__ dstb,
                       int E, int N) {
    for (int e = blockIdx.x * blockDim.x + threadIdx.x; e < 2 * E;
         e += gridDim.x * blockDim.x) {
        int d, s;
        if (e < E) {
            d = __ldg(dsta + e);
            s = __ldg(srca + e);
        } else {
            d = __ldg(dstb + e - E) + N;
            s = __ldg(srcb + e - E) + N;
        }
        int p = atomicAdd(&g_cursor[d], 1);
        g_perm[p] = s;
    }
}

// ---------------- coalesced gather + BN affine: h[n] = sc*(y[n]+sum_nb) + (deg+1)*sf ----------------
__global__ void __launch_bounds__(256) k_gather(
    const float* __restrict__ gammaP, const float* __restrict__ betaP,
    const float* __restrict__ sumsPA, const float* __restrict__ sumsPB,
    int N, int NN, float invN) {
    __shared__ float sscA[32], ssfA[32], sscB[32], ssfB[32];
    if (threadIdx.x < 64) {
        int c = threadIdx.x & 31;
        bool isB = threadIdx.x >= 32;
        const float* sumsP = isB ? sumsPB : sumsPA;
        float sc = 0.f, sf = 0.f;
        if (c < DIM) {
            sc = 1.f;
            if (sumsP) {
                float m = sumsP[c] * invN;
                float var = sumsP[PAD + c] * invN - m * m;
                float istd = rsqrtf(var + BN_EPS);
                sc = gammaP[c] * istd;
                sf = betaP[c] - m * sc;
            }
        }
        if (isB) {
            sscB[c] = sc;
            ssfB[c] = sf;
        } else {
            sscA[c] = sc;
            ssfA[c] = sf;
        }
    }
    __syncthreads();
    int t = blockIdx.x * 256 + threadIdx.x;
    int n = t >> 3, g = t & 7;
    if (n >= NN) return;
    int c0 = g * 4;
    float4 acc = *(const float4*)(g_y + (size_t)n * PAD + c0);
    int beg = __ldg(g_rowptr + n), end = __ldg(g_cursor + n);
    int p = beg;
    for (; p + 1 < end; p += 2) {
        int s0 = __ldg(g_perm + p);
        int s1 = __ldg(g_perm + p + 1);
        float4 v0 = *(const float4*)(g_y + (size_t)s0 * PAD + c0);
        float4 v1 = *(const float4*)(g_y + (size_t)s1 * PAD + c0);
        acc.x += v0.x + v1.x;
        acc.y += v0.y + v1.y;
        acc.z += v0.z + v1.z;
        acc.w += v0.w + v1.w;
    }
    if (p < end) {
        int s0 = __ldg(g_perm + p);
        float4 v0 = *(const float4*)(g_y + (size_t)s0 * PAD + c0);
        acc.x += v0.x;
        acc.y += v0.y;
        acc.z += v0.z;
        acc.w += v0.w;
    }
    float dp1 = (float)(end - beg) + 1.f;
    const float* sc = (n >= N) ? sscB : sscA;
    const float* sf = (n >= N) ? ssfB : ssfA;
    float4 hv;
    hv.x = sc[c0 + 0] * acc.x + dp1 * sf[c0 + 0];
    hv.y = sc[c0 + 1] * acc.y + dp1 * sf[c0 + 1];
    hv.z = sc[c0 + 2] * acc.z + dp1 * sf[c0 + 2];
    hv.w = sc[c0 + 3] * acc.w + dp1 * sf[c0 + 3];
    *(float4*)(g_h + (size_t)n * PAD + c0) = hv;
}

// ---------------- MLP (round-15 phase B): 2 nodes/thread, stats, pool ----------------
__global__ void __launch_bounds__(128, 3)
k_mlp(const float* __restrict__ W1, const float* __restrict__ b1,
      const float* __restrict__ W2, const float* __restrict__ b2,
      float* __restrict__ sumsC,
      const int* __restrict__ batchA, const int* __restrict__ batchB,
      int N, int G, int NPBh) {
    __shared__ ulonglong2 sW1x[31 * 8], sW2x[31 * 8];
    __shared__ u64 sb1p[16], sb2p[16];
    __shared__ float sstat[16 * 64];

    bool brB = blockIdx.x >= NPBh;

    for (int idx = threadIdx.x; idx < 31 * 8; idx += 128) {
        int i = idx >> 3, q = idx & 7;
        int c0 = 4 * q;
        float w0 = W1[i * 31 + c0];
        float w1 = (c0 + 1 < 31) ? W1[i * 31 + c0 + 1] : 0.f;
        float w2 = (c0 + 2 < 31) ? W1[i * 31 + c0 + 2] : 0.f;
        float w3 = (c0 + 3 < 31) ? W1[i * 31 + c0 + 3] : 0.f;
        ulonglong2 pp;
        PACK2(pp.x, w0, w1);
        PACK2(pp.y, w2, w3);
        sW1x[idx] = pp;
        w0 = W2[i * 31 + c0];
        w1 = (c0 + 1 < 31) ? W2[i * 31 + c0 + 1] : 0.f;
        w2 = (c0 + 2 < 31) ? W2[i * 31 + c0 + 2] : 0.f;
        w3 = (c0 + 3 < 31) ? W2[i * 31 + c0 + 3] : 0.f;
        PACK2(pp.x, w0, w1);
        PACK2(pp.y, w2, w3);
        sW2x[idx] = pp;
    }
    if (threadIdx.x < 16) {
        int o = threadIdx.x;
        float lo = b1[2 * o];
        float hi = (2 * o + 1 < 31) ? b1[2 * o + 1] : 0.f;
        u64 p;
        PACK2(p, lo, hi);
        sb1p[o] = p;
        lo = b2[2 * o];
        hi = (2 * o + 1 < 31) ? b2[2 * o + 1] : 0.f;
        PACK2(p, lo, hi);
        sb2p[o] = p;
    }
    __syncthreads();

    int blk = brB ? (blockIdx.x - NPBh) : blockIdx.x;
    int lnA = blk * 256 + 2 * threadIdx.x;
    int lnB = lnA + 1;
    bool actA = lnA < N, actB = lnB < N;
    int off = brB ? N : 0;
    int nA = (actA ? lnA : (N - 1)) + off;
    int nB = (actB ? lnB : (N - 1)) + off;

    bool doPool = (batchA != nullptr);
    int bA = -1, bB = -1;
    if (doPool) {
        if (actA) bA = brB ? (__ldg(batchB + lnA) + G) : __ldg(batchA + lnA);
        if (actB) bB = brB ? (__ldg(batchB + lnB) + G) : __ldg(batchA + lnB);
    }
    int b0 = __shfl_sync(0xffffffffu, bA, 0);
    bool uniform = doPool && (b0 >= 0) &&
                   __all_sync(0xffffffffu,
                              ((bA == b0) || (bA < 0)) && ((bB == b0) || (bB < 0)));
    int cntAct = __popc(__ballot_sync(0xffffffffu, actA)) +
                 __popc(__ballot_sync(0xffffffffu, actB));

    // ---- load MLP-ready inputs from g_h ----
    u64 ha[16], hb[16];
    {
        const ulonglong2* sr = (const ulonglong2*)(g_h + (size_t)nA * PAD);
#pragma unroll
        for (int q = 0; q < 8; q++) {
            ulonglong2 v = sr[q];
            ha[2 * q] = v.x;
            ha[2 * q + 1] = v.y;
        }
        sr = (const ulonglong2*)(g_h + (size_t)nB * PAD);
#pragma unroll
        for (int q = 0; q < 8; q++) {
            ulonglong2 v = sr[q];
            hb[2 * q] = v.x;
            hb[2 * q + 1] = v.y;
        }
    }

    // ---- layer 1 (shared weight loads feed both nodes) ----
    u64 aA[16], aB[16];
#pragma unroll
    for (int o = 0; o < 16; o++) {
        aA[o] = sb1p[o];
        aB[o] = sb1p[o];
    }
#pragma unroll
    for (int j = 0; j < 16; j++) {
        float xA0, xA1, xB0, xB1;
        UNPACK2(xA0, xA1, ha[j]);
        UNPACK2(xB0, xB1, hb[j]);
        u64 xpA, xpB;
        PACK2(xpA, xA0, xA0);
        PACK2(xpB, xB0, xB0);
        const ulonglong2* wr = sW1x + (2 * j) * 8;
#pragma unroll
        for (int q = 0; q < 8; q++) {
            ulonglong2 wv = wr[q];
            FMA2(aA[2 * q], xpA, wv.x, aA[2 * q]);
            FMA2(aA[2 * q + 1], xpA, wv.y, aA[2 * q + 1]);
            FMA2(aB[2 * q], xpB, wv.x, aB[2 * q]);
            FMA2(aB[2 * q + 1], xpB, wv.y, aB[2 * q + 1]);
        }
        if (j < 15) {
            PACK2(xpA, xA1, xA1);
            PACK2(xpB, xB1, xB1);
            wr = sW1x + (2 * j + 1) * 8;
#pragma unroll
            for (int q = 0; q < 8; q++) {
                ulonglong2 wv = wr[q];
                FMA2(aA[2 * q], xpA, wv.x, aA[2 * q]);
                FMA2(aA[2 * q + 1], xpA, wv.y, aA[2 * q + 1]);
                FMA2(aB[2 * q], xpB, wv.x, aB[2 * q]);
                FMA2(aB[2 * q + 1], xpB, wv.y, aB[2 * q + 1]);
            }
        }
    }
#pragma unroll
    for (int o = 0; o < 16; o++) {
        float lo, hi;
        UNPACK2(lo, hi, aA[o]);
        PACK2(ha[o], fmaxf(lo, 0.f), fmaxf(hi, 0.f));
        UNPACK2(lo, hi, aB[o]);
        PACK2(hb[o], fmaxf(lo, 0.f), fmaxf(hi, 0.f));
    }

    // ---- layer 2 ----
#pragma unroll
    for (int o = 0; o < 16; o++) {
        aA[o] = sb2p[o];
        aB[o] = sb2p[o];
    }
#pragma unroll
    for (int j = 0; j < 16; j++) {
        float xA0, xA1, xB0, xB1;
        UNPACK2(xA0, xA1, ha[j]);
        UNPACK2(xB0, xB1, hb[j]);
        u64 xpA, xpB;
        PACK2(xpA, xA0, xA0);
        PACK2(xpB, xB0, xB0);
        const ulonglong2* wr = sW2x + (2 * j) * 8;
#pragma unroll
        for (int q = 0; q < 8; q++) {
            ulonglong2 wv = wr[q];
            FMA2(aA[2 * q], xpA, wv.x, aA[2 * q]);
            FMA2(aA[2 * q + 1], xpA, wv.y, aA[2 * q + 1]);
            FMA2(aB[2 * q], xpB, wv.x, aB[2 * q]);
            FMA2(aB[2 * q + 1], xpB, wv.y, aB[2 * q + 1]);
        }
        if (j < 15) {
            PACK2(xpA, xA1, xA1);
            PACK2(xpB, xB1, xB1);
            wr = sW2x + (2 * j + 1) * 8;
#pragma unroll
            for (int q = 0; q < 8; q++) {
                ulonglong2 wv = wr[q];
                FMA2(aA[2 * q], xpA, wv.x, aA[2 * q]);
                FMA2(aA[2 * q + 1], xpA, wv.y, aA[2 * q + 1]);
                FMA2(aB[2 * q], xpB, wv.x, aB[2 * q]);
                FMA2(aB[2 * q + 1], xpB, wv.y, aB[2 * q + 1]);
            }
        }
    }

    // ---- relu + mask + store + stats (+pool on layer 4) ----
    int wid = threadIdx.x >> 5, lane = threadIdx.x & 31;
    float amA = actA ? 1.f : 0.f, amB = actB ? 1.f : 0.f;
    float4* outA = (float4*)(g_y + (size_t)nA * PAD);
    float4* outB = (float4*)(g_y + (size_t)nB * PAD);
    float pA0 = 0.f, pA1 = 0.f, pB0 = 0.f, pB1 = 0.f;
#pragma unroll
    for (int o = 0; o < 16; o++) {
        float loA, hiA, loB, hiB;
        UNPACK2(loA, hiA, aA[o]);
        UNPACK2(loB, hiB, aB[o]);
        loA = fmaxf(loA, 0.f) * amA;
        hiA = fmaxf(hiA, 0.f) * amA;
        loB = fmaxf(loB, 0.f) * amB;
        hiB = fmaxf(hiB, 0.f) * amB;
        if (o == 15) { hiA = 0.f; hiB = 0.f; }  // col 31 padding
        float s0 = loA + loB, q0 = loA * loA + loB * loB;
        float s1 = hiA + hiB, q1 = hiA * hiA + hiB * hiB;
#pragma unroll
        for (int offX = 16; offX >= 4; offX >>= 1) {
            s0 += __shfl_xor_sync(0xffffffffu, s0, offX);
            q0 += __shfl_xor_sync(0xffffffffu, q0, offX);
            s1 += __shfl_xor_sync(0xffffffffu, s1, offX);
            q1 += __shfl_xor_sync(0xffffffffu, q1, offX);
        }
        if (lane < 4) {
            sstat[(wid * 4 + lane) * 64 + 2 * o + 0] = s0;
            sstat[(wid * 4 + lane) * 64 + 32 + 2 * o + 0] = q0;
            sstat[(wid * 4 + lane) * 64 + 2 * o + 1] = s1;
            sstat[(wid * 4 + lane) * 64 + 32 + 2 * o + 1] = q1;
        }
        if (doPool) {
            if (uniform) {
                s0 += __shfl_xor_sync(0xffffffffu, s0, 2);
                s0 += __shfl_xor_sync(0xffffffffu, s0, 1);
                s1 += __shfl_xor_sync(0xffffffffu, s1, 2);
                s1 += __shfl_xor_sync(0xffffffffu, s1, 1);
                if (lane == 0) {
                    atomicAdd(&g_pooled[(size_t)b0 * PAD + 2 * o], s0);
                    if (2 * o + 1 < DIM)
                        atomicAdd(&g_pooled[(size_t)b0 * PAD + 2 * o + 1], s1);
                }
            } else {
                if (actA) {
                    atomicAdd(&g_pooled[(size_t)bA * PAD + 2 * o], loA);
                    if (2 * o + 1 < DIM)
                        atomicAdd(&g_pooled[(size_t)bA * PAD + 2 * o + 1], hiA);
                }
                if (actB) {
                    atomicAdd(&g_pooled[(size_t)bB * PAD + 2 * o], loB);
                    if (2 * o + 1 < DIM)
                        atomicAdd(&g_pooled[(size_t)bB * PAD + 2 * o + 1], hiB);
                }
            }
        }
        if ((o & 1) == 0) {
            pA0 = loA;
            pA1 = hiA;
            pB0 = loB;
            pB1 = hiB;
        } else {
            if (actA) outA[o >> 1] = make_float4(pA0, pA1, loA, hiA);
            if (actB) outB[o >> 1] = make_float4(pB0, pB1, loB, hiB);
        }
    }
    if (doPool) {
        if (uniform) {
            if (lane == 0) atomicAdd(&g_gcnt[b0], (float)cntAct);
        } else {
            if (actA) atomicAdd(&g_gcnt[bA], 1.f);
            if (actB) atomicAdd(&g_gcnt[bB], 1.f);
        }
    }
    __syncthreads();
    if (threadIdx.x < 64) {
        float t = 0.f;
#pragma unroll
        for (int r = 0; r < 16; r++) t += sstat[r * 64 + threadIdx.x];
        atomicAdd(&sumsC[(brB ? 64 : 0) + threadIdx.x], t);
    }
}

// ---------------- per-graph fc with per-branch layer-4 BN affine ----------------
__global__ void k_fcbr(const float* __restrict__ W, const float* __restrict__ bb,
                       const float* __restrict__ gamma4, const float* __restrict__ beta4,
                       float* __restrict__ out, int G, float invN) {
    __shared__ float p[PAD];
    int g = blockIdx.x;  // 0..2G-1
    if (threadIdx.x < PAD) {
        int c = threadIdx.x;
        float val = 0.f;
        if (c < DIM) {
            const float* s = g_sums + 4 * 128 + ((g >= G) ? 64 : 0);
            float m = s[c] * invN;
            float var = s[PAD + c] * invN - m * m;
            float istd = rsqrtf(var + BN_EPS);
            float sc = gamma4[c] * istd;
            float sf = beta4[c] - m * sc;
            val = g_pooled[(size_t)g * PAD + c] * sc + g_gcnt[g] * sf;
        }
        p[c] = val;
    }
    __syncthreads();
    int o = threadIdx.x;
    float acc = __ldg(bb + o);
#pragma unroll
    for (int i = 0; i < DIM; i++) acc += p[i] * __ldg(W + i * 256 + o);
    out[(size_t)g * 256 + o] = fmaxf(acc, 0.f);
}

// ---------------- tiled SGEMM (f32x2): C = act((A [+A2]) @ B + bias) ----------------
template <bool SUM2, bool RELU>
__global__ void k_gemm(const float* __restrict__ A, const float* __restrict__ A2,
                       const float* __restrict__ B, const float* __restrict__ bias,
                       float* __restrict__ C, int M, int N, int K) {
    const int BM = 64, BN = 64, BK = 16;
    __shared__ float As[BM][BK + 1];
    __shared__ float Bs[BK][BN];
    int tx = threadIdx.x % 16, ty = threadIdx.x / 16;
    int row0 = blockIdx.y * BM, col0 = blockIdx.x * BN;
    u64 acc2[4][2];
    u64 zero;
    PACK2(zero, 0.f, 0.f);
#pragma unroll
    for (int u = 0; u < 4; u++) {
        acc2[u][0] = zero;
        acc2[u][1] = zero;
    }
    for (int k0 = 0; k0 < K; k0 += BK) {
        for (int i = threadIdx.x; i < BM * BK; i += 256) {
            int r = i / BK, c = i % BK;
            float v = A[(size_t)(row0 + r) * K + k0 + c];
            if (SUM2) v += A2[(size_t)(row0 + r) * K + k0 + c];
            As[r][c] = v;
        }
        for (int i = threadIdx.x; i < BK * BN; i += 256) {
            int r = i / BN, c = i % BN;
            Bs[r][c] = B[(size_t)(k0 + r) * N + col0 + c];
        }
        __syncthreads();
#pragma unroll
        for (int k = 0; k < BK; k++) {
            u64 b0 = *(const u64*)&Bs[k][tx * 4];
            u64 b1 = *(const u64*)&Bs[k][tx * 4 + 2];
#pragma unroll
            for (int u = 0; u < 4; u++) {
                float a = As[ty * 4 + u][k];
                u64 ap;
                PACK2(ap, a, a);
                FMA2(acc2[u][0], ap, b0, acc2[u][0]);
                FMA2(acc2[u][1], ap, b1, acc2[u][1]);
            }
        }
        __syncthreads();
    }
#pragma unroll
    for (int u = 0; u < 4; u++) {
        int r = row0 + ty * 4 + u;
#pragma unroll
        for (int w = 0; w < 2; w++) {
            float lo, hi;
            UNPACK2(lo, hi, acc2[u][w]);
            int cc = col0 + tx * 4 + 2 * w;
            float v0 = lo + bias[cc];
            float v1 = hi + bias[cc + 1];
            if (RELU) {
                v0 = fmaxf(v0, 0.f);
                v1 = fmaxf(v1, 0.f);
            }
            C[(size_t)r * N + cc] = v0;
            C[(size_t)r * N + cc + 1] = v1;
        }
    }
}

// ---------------- final projection + restore zero-state for next replay ----------------
__global__ void k_out(const float* __restrict__ W, const float* __restrict__ b,
                      float* __restrict__ out, int G, int NN) {
    __shared__ float sW[512];
    for (int i = threadIdx.x; i < 512; i += blockDim.x) sW[i] = W[i];
    __syncthreads();
    int g = blockIdx.x * blockDim.x + threadIdx.x;
    if (g < G) {
        const float4* row = (const float4*)(g_c2 + (size_t)g * 256);
        float a0 = b[0], a1 = b[1];
#pragma unroll 8
        for (int i = 0; i < 64; i++) {
            float4 v = row[i];
            int o = i * 4;
            a0 += v.x * sW[2 * o + 0] + v.y * sW[2 * o + 2] + v.z * sW[2 * o + 4] + v.w * sW[2 * o + 6];
            a1 += v.x * sW[2 * o + 1] + v.y * sW[2 * o + 3] + v.z * sW[2 * o + 5] + v.w * sW[2 * o + 7];
        }
        out[g * 2 + 0] = a0;
        out[g * 2 + 1] = a1;
    }
    // restore zero state (consumed-and-reset invariant)
    int stride = gridDim.x * blockDim.x;
    int tid0 = blockIdx.x * blockDim.x + threadIdx.x;
    for (int t = tid0; t < NN; t += stride) g_cnt[t] = 0;
    for (int t = tid0; t < 2 * GMAX * PAD; t += stride) g_pooled[t] = 0.f;
    for (int t = tid0; t < 2 * GMAX; t += stride) g_gcnt[t] = 0.f;
    for (int t = tid0; t < 5 * 128; t += stride) g_sums[t] = 0.f;
    if (tid0 == 0) g_total = 0;
}

// ---------------- launch ----------------
extern "C" void kernel_launch(void* const* d_in, const int* in_sizes, int n_in,
                              void* d_out, int out_size) {
    const float* x_a = (const float*)d_in[0];
    const int* ei_a = (const int*)d_in[1];
    const int* batch_a = (const int*)d_in[2];
    const float* x_b = (const float*)d_in[3];
    const int* ei_b = (const int*)d_in[4];
    const int* batch_b = (const int*)d_in[5];
    const float* W1s = (const float*)d_in[6];
    const float* b1s = (const float*)d_in[7];
    const float* W2s = (const float*)d_in[8];
    const float* b2s = (const float*)d_in[9];
    const float* gammas = (const float*)d_in[10];
    const float* betas = (const float*)d_in[11];
    const float* fcxW = (const float*)d_in[12];
    const float* fcxb = (const float*)d_in[13];
    const float* fc1W = (const float*)d_in[14];
    const float* fc1b = (const float*)d_in[15];
    const float* fc2W = (const float*)d_in[16];
    const float* fc2b = (const float*)d_in[17];
    const float* outW = (const float*)d_in[18];
    const float* outb = (const float*)d_in[19];

    int N = in_sizes[0] / DIM;
    int E = in_sizes[1] / 2;
    int G = out_size / 2;
    int NN = 2 * N;
    float invN = 1.f / (float)N;
    int NPBh = (N + 255) / 256;  // 256 nodes per block (2/thread)

    float* sums_ptr;
    float* ha_ptr;
    float* c1_ptr;
    float* c2_ptr;
    cudaGetSymbolAddress((void**)&sums_ptr, g_sums);
    cudaGetSymbolAddress((void**)&ha_ptr, g_ha);
    cudaGetSymbolAddress((void**)&c1_ptr, g_c1);
    cudaGetSymbolAddress((void**)&c2_ptr, g_c2);

    k_count<<<2048, 256>>>(ei_a + E, ei_b + E, E, N);
    k_assign<<<(NN + 511) / 512, 512>>>(x_a, x_b, N, NN);
    k_fill<<<2048, 256>>>(ei_a, ei_a + E, ei_b, ei_b + E, E, N);

    for (int l = 0; l < 5; l++) {
        const float* sA = (l == 0) ? nullptr : sums_ptr + (l - 1) * 128;
        const float* sB = (l == 0) ? nullptr : sums_ptr + (l - 1) * 128 + 64;
        const float* gP = (l == 0) ? nullptr : gammas + (l - 1) * DIM;
        const float* bP = (l == 0) ? nullptr : betas + (l - 1) * DIM;
        const int* pA = (l == 4) ? batch_a : nullptr;
        const int* pB = (l == 4) ? batch_b : nullptr;
        k_gather<<<(NN * 8 + 255) / 256, 256>>>(gP, bP, sA, sB, N, NN, invN);
        k_mlp<<<2 * NPBh, 128>>>(W1s + l * DIM * DIM, b1s + l * DIM,
                                 W2s + l * DIM * DIM, b2s + l * DIM,
                                 sums_ptr + l * 128, pA, pB, N, G, NPBh);
    }

    k_fcbr<<<2 * G, 256>>>(fcxW, fcxb, gammas + 4 * DIM, betas + 4 * DIM,
                           ha_ptr, G, invN);

    dim3 g1(1024 / 64, G / 64);
    k_gemm<true, true><<<g1, 256>>>(ha_ptr, ha_ptr + (size_t)G * 256, fc1W, fc1b,
                                    c1_ptr, G, 1024, 256);
    dim3 g2(256 / 64, G / 64);
    k_gemm<false, true><<<g2, 256>>>(c1_ptr, nullptr, fc2W, fc2b, c2_ptr, G, 256, 1024);
    k_out<<<1024, 256>>>(outW, outb, (float*)d_out, G, NN);
}